// round 10
// baseline (speedup 1.0000x reference)
#include <cuda_runtime.h>
#include <cuda_fp16.h>
#include <cstdint>

// B=8, N=512, T=64, D=128, H=8, DK=16, K=3.
// TWO (b,n) tiles per CTA (M=128), 512 thr = 16 warps, warp tile 32x32.
// fp16 MMA operands (11-bit significand == tf32), fp32 accumulate.
// R10: software-pipelined weight staging (reg prefetch + double-buffered S_ST).

// byte offsets in dynamic smem
#define S_IN_B   0          // 136 rows x 272B fp16. pad rows 0,1,66-69,134,135 zero.
#define S_ST_B   36992      // 2 x 32KB double-buffered packed-B chunk
#define S_QP_B   102528     // 128 x 272B fp16 q tile
#define S_KP_B   137344     // 2 x 16KB packed K^T B-frags
#define S_VP_B   170112     // 2 x 16KB packed V B-frags
#define S_MSK_B  202880     // 64 x ull row masks
#define SMEM_BYTES 203392

// g_pack chunk offsets (uint32 units; each chunk = 8192 uint32 = 32KB)
#define PQ4 0
#define PK4 24576
#define PV4 49152
#define PO4 57344

typedef unsigned long long ull;
__device__ uint32_t g_pack[65536];

// ---------------- PTX helpers ----------------
__device__ __forceinline__ uint32_t smem_u32(const void* p) {
    uint32_t a;
    asm("{ .reg .u64 t; cvta.to.shared.u64 t, %1; cvt.u32.u64 %0, t; }" : "=r"(a) : "l"(p));
    return a;
}
__device__ __forceinline__ uint32_t h2(float lo, float hi) {
    uint32_t r; asm("cvt.rn.f16x2.f32 %0, %1, %2;" : "=r"(r) : "f"(hi), "f"(lo)); return r;
}
__device__ __forceinline__ uint4 lds128(uint32_t a) {
    uint4 v;
    asm volatile("ld.shared.v4.b32 {%0,%1,%2,%3}, [%4];"
                 : "=r"(v.x), "=r"(v.y), "=r"(v.z), "=r"(v.w) : "r"(a));
    return v;
}
__device__ __forceinline__ void ldsm4(uint32_t (&r)[4], uint32_t a) {
    asm volatile("ldmatrix.sync.aligned.m8n8.x4.shared.b16 {%0,%1,%2,%3}, [%4];"
                 : "=r"(r[0]), "=r"(r[1]), "=r"(r[2]), "=r"(r[3]) : "r"(a));
}
__device__ __forceinline__ void mma16(float (&c)[4], const uint32_t (&a)[4],
                                      uint32_t b0, uint32_t b1) {
    asm volatile(
        "mma.sync.aligned.m16n8k16.row.col.f32.f16.f16.f32 "
        "{%0,%1,%2,%3},{%4,%5,%6,%7},{%8,%9},{%0,%1,%2,%3};"
        : "+f"(c[0]), "+f"(c[1]), "+f"(c[2]), "+f"(c[3])
        : "r"(a[0]), "r"(a[1]), "r"(a[2]), "r"(a[3]), "r"(b0), "r"(b1));
}

// ---------------- prep: pack weights as fp16 B-fragments ----------------
__global__ void prep_kernel(const float* __restrict__ Wq, const float* __restrict__ Wk,
                            const float* __restrict__ Wv, const float* __restrict__ Wo) {
    int idx = blockIdx.x * blockDim.x + threadIdx.x;   // 16384
    if (idx >= 16384) return;
    const float* W; int base4, within, j = 0, conv; float sc = 1.0f;
    if (idx < 6144)       { W = Wq; j = idx >> 11; within = idx & 2047; base4 = PQ4 / 4 + idx; conv = 1; sc = 0.25f; }
    else if (idx < 12288) { int i2 = idx - 6144; W = Wk; j = i2 >> 11; within = i2 & 2047; base4 = PK4 / 4 + i2; conv = 1; }
    else if (idx < 14336) { int i2 = idx - 12288; W = Wv; within = i2; base4 = PV4 / 4 + i2; conv = 0; }
    else                  { int i2 = idx - 14336; W = Wo; within = i2; base4 = PO4 / 4 + i2; conv = 0; }
    int lane = within & 31, njp = (within >> 5) & 7, ksp = within >> 8;
    int n0 = njp * 16 + (lane >> 2);
    int n1 = n0 + 8;
    int k0 = ksp * 16 + 2 * (lane & 3);
    float w[8];
    if (conv) {
        w[0] = W[(n0 * 128 + k0) * 3 + j];     w[1] = W[(n0 * 128 + k0 + 1) * 3 + j];
        w[2] = W[(n0 * 128 + k0 + 8) * 3 + j]; w[3] = W[(n0 * 128 + k0 + 9) * 3 + j];
        w[4] = W[(n1 * 128 + k0) * 3 + j];     w[5] = W[(n1 * 128 + k0 + 1) * 3 + j];
        w[6] = W[(n1 * 128 + k0 + 8) * 3 + j]; w[7] = W[(n1 * 128 + k0 + 9) * 3 + j];
    } else {
        w[0] = W[n0 * 128 + k0];     w[1] = W[n0 * 128 + k0 + 1];
        w[2] = W[n0 * 128 + k0 + 8]; w[3] = W[n0 * 128 + k0 + 9];
        w[4] = W[n1 * 128 + k0];     w[5] = W[n1 * 128 + k0 + 1];
        w[6] = W[n1 * 128 + k0 + 8]; w[7] = W[n1 * 128 + k0 + 9];
    }
    uint4 o;
    o.x = h2(w[0] * sc, w[1] * sc);
    o.y = h2(w[2] * sc, w[3] * sc);
    o.z = h2(w[4] * sc, w[5] * sc);
    o.w = h2(w[6] * sc, w[7] * sc);
    ((uint4*)g_pack)[base4] = o;
}

// ---------------- pipelined staging helpers ----------------
__device__ __forceinline__ void ldgB(uint4 (&rb)[4], const uint4* __restrict__ g4, int tid) {
#pragma unroll
    for (int r = 0; r < 4; r++) rb[r] = g4[tid + r * 512];
}
__device__ __forceinline__ void stsB(char* smc, int buf, const uint4 (&rb)[4], int tid) {
#pragma unroll
    for (int r = 0; r < 4; r++)
        *(uint4*)(smc + S_ST_B + buf * 32768 + (tid + r * 512) * 16) = rb[r];
}
__device__ __forceinline__ void ldgIN(uint2 (&iv)[8], const float* __restrict__ g, int tid) {
#pragma unroll
    for (int r = 0; r < 8; r++) {
        float4 f = *(const float4*)(g + (tid + r * 512) * 4);
        iv[r].x = h2(f.x, f.y);
        iv[r].y = h2(f.z, f.w);
    }
}
__device__ __forceinline__ void stsIN(char* smc, const uint2 (&iv)[8], int tid) {
#pragma unroll
    for (int r = 0; r < 8; r++) {
        int idx = tid + r * 512;
        int tile = idx >> 11, within = idx & 2047;
        int t = within >> 5, d = (within & 31) * 4;
        int row = (tile ? 70 : 2) + t;
        *(uint2*)(smc + S_IN_B + row * 272 + d * 2) = iv[r];
    }
}

// one K=128 chunk, warp tile 32x32
__device__ __forceinline__ void mma_chunk(float (&acc)[2][4][4], uint32_t a0, uint32_t b0) {
#pragma unroll
    for (int ksp = 0; ksp < 8; ksp++) {
        uint32_t A0[4], A1[4];
        ldsm4(A0, a0 + ksp * 32);
        ldsm4(A1, a0 + 16 * 272 + ksp * 32);
        uint4 B01 = lds128(b0 + ksp * 4096);
        uint4 B23 = lds128(b0 + ksp * 4096 + 512);
        mma16(acc[0][0], A0, B01.x, B01.y);
        mma16(acc[0][1], A0, B01.z, B01.w);
        mma16(acc[0][2], A0, B23.x, B23.y);
        mma16(acc[0][3], A0, B23.z, B23.w);
        mma16(acc[1][0], A1, B01.x, B01.y);
        mma16(acc[1][1], A1, B01.z, B01.w);
        mma16(acc[1][2], A1, B23.x, B23.y);
        mma16(acc[1][3], A1, B23.z, B23.w);
    }
}
__device__ __forceinline__ void zacc(float (&acc)[2][4][4]) {
#pragma unroll
    for (int s = 0; s < 2; s++)
#pragma unroll
        for (int i = 0; i < 4; i++)
#pragma unroll
            for (int k = 0; k < 4; k++) acc[s][i][k] = 0.f;
}
// ---------------- epilogues (same layouts as R9) ----------------
__device__ __forceinline__ void epi_q(char* smc, const float* __restrict__ bq,
                                      float (&acc)[2][4][4], int lane, int mg, int ng) {
#pragma unroll
    for (int msub = 0; msub < 2; msub++) {
        int r0 = mg * 32 + msub * 16 + (lane >> 2);
#pragma unroll
        for (int nt = 0; nt < 4; nt++) {
            int col = ng * 32 + nt * 8 + (lane & 3) * 2;
            float2 bb = *(const float2*)(bq + col);
            *(uint32_t*)(smc + S_QP_B + r0 * 272 + col * 2) =
                h2(acc[msub][nt][0] + bb.x * 0.25f, acc[msub][nt][1] + bb.y * 0.25f);
            *(uint32_t*)(smc + S_QP_B + (r0 + 8) * 272 + col * 2) =
                h2(acc[msub][nt][2] + bb.x * 0.25f, acc[msub][nt][3] + bb.y * 0.25f);
        }
    }
}
__device__ __forceinline__ void epi_k(char* smc, const float* __restrict__ bk,
                                      float (&acc)[2][4][4], int lane, int mg, int ng) {
#pragma unroll
    for (int msub = 0; msub < 2; msub++) {
#pragma unroll
        for (int nt = 0; nt < 4; nt++) {
#pragma unroll
            for (int i = 0; i < 4; i++) {
                int s = mg * 32 + msub * 16 + (lane >> 2) + (i >> 1) * 8;
                int col = ng * 32 + nt * 8 + (lane & 3) * 2 + (i & 1);
                int tile = s >> 6, st = s & 63;
                int h = col >> 4, dk = col & 15;
                int ntb = st >> 3, ntp = ntb >> 1;
                int lp = ((st & 7) << 2) | ((dk >> 1) & 3);
                int off = tile * 16384 + ((h * 4 + ntp) * 32 + lp) * 16
                        + (ntb & 1) * 8 + (dk >> 3) * 4 + (dk & 1) * 2;
                *(__half*)(smc + S_KP_B + off) =
                    __float2half_rn(acc[msub][nt][i] + __ldg(bk + col));
            }
        }
    }
}
__device__ __forceinline__ void epi_v(char* smc, const float* __restrict__ bv,
                                      float (&acc)[2][4][4], int lane, int mg, int ng) {
#pragma unroll
    for (int msub = 0; msub < 2; msub++) {
#pragma unroll
        for (int nt = 0; nt < 4; nt++) {
#pragma unroll
            for (int i = 0; i < 4; i++) {
                int s = mg * 32 + msub * 16 + (lane >> 2) + (i >> 1) * 8;
                int col = ng * 32 + nt * 8 + (lane & 3) * 2 + (i & 1);
                int tile = s >> 6, st = s & 63;
                int h = col >> 4, dk = col & 15;
                int ksp = st >> 4, ntv = dk >> 3;
                int lp = ((dk & 7) << 2) | ((st >> 1) & 3);
                int off = tile * 16384 + ((h * 4 + ksp) * 32 + lp) * 16
                        + ntv * 8 + ((st >> 3) & 1) * 4 + (st & 1) * 2;
                *(__half*)(smc + S_VP_B + off) =
                    __float2half_rn(acc[msub][nt][i] + __ldg(bv + col));
            }
        }
    }
}
__device__ __forceinline__ void epi_g(float* __restrict__ dst, const float* __restrict__ bias,
                                      float (&acc)[2][4][4], int lane, int mg, int ng) {
#pragma unroll
    for (int msub = 0; msub < 2; msub++) {
        int r0 = mg * 32 + msub * 16 + (lane >> 2);
#pragma unroll
        for (int nt = 0; nt < 4; nt++) {
            int col = ng * 32 + nt * 8 + (lane & 3) * 2;
            float2 bb = *(const float2*)(bias + col);
            float* d0 = dst + (r0 >> 6) * 8192 + (r0 & 63) * 128 + col;
            float* d1 = dst + ((r0 + 8) >> 6) * 8192 + ((r0 + 8) & 63) * 128 + col;
            *(float2*)d0 = make_float2(acc[msub][nt][0] + bb.x, acc[msub][nt][1] + bb.y);
            *(float2*)d1 = make_float2(acc[msub][nt][2] + bb.x, acc[msub][nt][3] + bb.y);
        }
    }
}

__global__ void __launch_bounds__(512, 1)
attn_kernel(const float* __restrict__ query, const float* __restrict__ key,
            const float* __restrict__ value, const int* __restrict__ mask,
            const float* __restrict__ bq, const float* __restrict__ bk,
            const float* __restrict__ bv, const float* __restrict__ bo,
            float* __restrict__ out)
{
    extern __shared__ char smc[];
    uint32_t smb = smem_u32(smc);
    const int tid = threadIdx.x, lane = tid & 31, wid = tid >> 5;
    const int cta = blockIdx.x, b = cta >> 8;
    const long long base = (long long)cta * 16384;

    const int mg = wid >> 2, ng = wid & 3;
    const int rowbase = (mg & 1) * 32 + (lane & 15) + ((mg >> 1) ? 68 : 0);
    const uint32_t a_thr = smb + S_IN_B + (uint32_t)(rowbase * 272 + (lane >> 4) * 16);
    const uint32_t b_lane_off = (uint32_t)((ng * 64 + lane) * 16);
    const uint32_t b_buf0 = smb + S_ST_B + b_lane_off;
    const uint32_t b_buf1 = smb + S_ST_B + 32768u + b_lane_off;

    // ---- prologue: pads, masks, value input + PV chunk ----
    if (tid < 544) {
        int rr = tid / 68, off = tid - rr * 68;
        int row = (rr < 2) ? rr : ((rr < 6) ? (64 + rr) : (128 + rr));
        *(uint32_t*)(smc + S_IN_B + row * 272 + off * 4) = 0u;
    }
    if (tid < 64) {
        ull m = 0;
        const int4* mr = (const int4*)(mask + b * 4096 + tid * 64);
#pragma unroll
        for (int u = 0; u < 16; u++) {
            int4 mm = mr[u];
            ull bits = (ull)(mm.x != 0) | ((ull)(mm.y != 0) << 1) |
                       ((ull)(mm.z != 0) << 2) | ((ull)(mm.w != 0) << 3);
            m |= bits << (u * 4);
        }
        *(ull*)(smc + S_MSK_B + tid * 8) = m;
    }
    uint4 rb[4];
    uint2 iv[8];
    ldgIN(iv, value + base, tid);
    ldgB(rb, (const uint4*)(g_pack + PV4), tid);
    stsIN(smc, iv, tid);
    stsB(smc, 0, rb, tid);
    __syncthreads();

    float acc[2][4][4];

    // ---- iter0: v GEMM (buf0) ; prefetch PQ0 + query input ----
    ldgB(rb, (const uint4*)(g_pack + PQ4), tid);
    ldgIN(iv, query + base, tid);
    zacc(acc);
    mma_chunk(acc, a_thr + 2 * 272, b_buf0);
    epi_v(smc, bv, acc, lane, mg, ng);
    __syncthreads();                      // all warps done reading S_IN(value)
    stsIN(smc, iv, tid);                  // query in
    stsB(smc, 1, rb, tid);                // PQ0 -> buf1
    __syncthreads();

    // ---- iter1: q tap0 (buf1) ; prefetch PQ1 ----
    ldgB(rb, (const uint4*)(g_pack + PQ4 + 8192), tid);
    zacc(acc);
    mma_chunk(acc, a_thr + 0 * 272, b_buf1);
    stsB(smc, 0, rb, tid);                // PQ1 -> buf0 (safe: buf0 idle since iter0 sync)
    __syncthreads();

    // ---- iter2: q tap1 (buf0) ; prefetch PQ2 ----
    ldgB(rb, (const uint4*)(g_pack + PQ4 + 16384), tid);
    mma_chunk(acc, a_thr + 1 * 272, b_buf0);
    stsB(smc, 1, rb, tid);
    __syncthreads();

    // ---- iter3: q tap2 (buf1) ; prefetch PK0 + key input ----
    ldgB(rb, (const uint4*)(g_pack + PK4), tid);
    ldgIN(iv, key + base, tid);
    mma_chunk(acc, a_thr + 2 * 272, b_buf1);
    epi_q(smc, bq, acc, lane, mg, ng);
    __syncthreads();                      // all warps done reading S_IN(query)
    stsIN(smc, iv, tid);                  // key in
    stsB(smc, 0, rb, tid);                // PK0 -> buf0
    __syncthreads();

    // ---- iter4: k tap1 (buf0) ; prefetch PK1 ----
    ldgB(rb, (const uint4*)(g_pack + PK4 + 8192), tid);
    zacc(acc);
    mma_chunk(acc, a_thr + 1 * 272, b_buf0);
    stsB(smc, 1, rb, tid);
    __syncthreads();

    // ---- iter5: k tap2 (buf1) ; prefetch PK2 ----
    ldgB(rb, (const uint4*)(g_pack + PK4 + 16384), tid);
    mma_chunk(acc, a_thr + 2 * 272, b_buf1);
    stsB(smc, 0, rb, tid);
    __syncthreads();

    // ---- iter6: k tap3 (buf0) ; prefetch PO -> buf1 ----
    ldgB(rb, (const uint4*)(g_pack + PO4), tid);
    mma_chunk(acc, a_thr + 3 * 272, b_buf0);
    epi_k(smc, bk, acc, lane, mg, ng);
    stsB(smc, 1, rb, tid);                // buf1 idle since iter5 sync
    __syncthreads();                      // KP/QP/VP + Wo visible

    // ---- attention: warp -> head (wid>>1), row half (wid&1)*32, both tiles ----
    {
        const int h = wid >> 1;
        const int mh = (wid & 1) * 32;
        const int r = lane >> 2, c = lane & 3;
#pragma unroll 1
        for (int tile = 0; tile < 2; tile++) {
            float pa[2][8][4];
#pragma unroll
            for (int mt = 0; mt < 2; mt++)
#pragma unroll
                for (int nt = 0; nt < 8; nt++)
#pragma unroll
                    for (int i = 0; i < 4; i++) pa[mt][nt][i] = 0.f;

            // QK^T
#pragma unroll
            for (int mt = 0; mt < 2; mt++) {
                uint32_t A[4];
                ldsm4(A, smb + S_QP_B
                         + (uint32_t)((tile * 64 + mh + mt * 16 + (lane & 15)) * 272
                                      + h * 32 + (lane >> 4) * 16));
#pragma unroll
                for (int ntp = 0; ntp < 4; ntp++) {
                    uint4 Bf = lds128(smb + S_KP_B
                                      + (uint32_t)(tile * 16384 + ((h * 4 + ntp) * 32 + lane) * 16));
                    mma16(pa[mt][2 * ntp], A, Bf.x, Bf.y);
                    mma16(pa[mt][2 * ntp + 1], A, Bf.z, Bf.w);
                }
            }

            // masked softmax
            float inv[2][2];
#pragma unroll
            for (int mt = 0; mt < 2; mt++) {
                ull mA = *(const ull*)(smc + S_MSK_B + (mh + mt * 16 + r) * 8);
                ull mB = *(const ull*)(smc + S_MSK_B + (mh + mt * 16 + r + 8) * 8);
                float mxA = -3.0e38f, mxB = -3.0e38f;
#pragma unroll
                for (int nt = 0; nt < 8; nt++) {
                    int c0 = nt * 8 + 2 * c, c1 = c0 + 1;
                    float v;
                    v = ((mA >> c0) & 1) ? pa[mt][nt][0] : -1.0e9f; pa[mt][nt][0] = v; mxA = fmaxf(mxA, v);
                    v = ((mA >> c1) & 1) ? pa[mt][nt][1] : -1.0e9f; pa[mt][nt][1] = v; mxA = fmaxf(mxA, v);
                    v = ((mB >> c0) & 1) ? pa[mt][nt][2] : -1.0e9f; pa[mt][nt][2] = v; mxB = fmaxf(mxB, v);
                    v = ((mB >> c1) & 1) ? pa[mt][nt][3] : -1.0e9f; pa[mt][nt][3] = v; mxB = fmaxf(mxB, v);
                }
                mxA = fmaxf(mxA, __shfl_xor_sync(0xffffffffu, mxA, 1));
                mxA = fmaxf(mxA, __shfl_xor_sync(0xffffffffu, mxA, 2));
                mxB = fmaxf(mxB, __shfl_xor_sync(0xffffffffu, mxB, 1));
                mxB = fmaxf(mxB, __shfl_xor_sync(0xffffffffu, mxB, 2));
                float sA = 0.f, sB = 0.f;
#pragma unroll
                for (int nt = 0; nt < 8; nt++) {
                    float e;
                    e = __expf(pa[mt][nt][0] - mxA); pa[mt][nt][0] = e; sA += e;
                    e = __expf(pa[mt][nt][1] - mxA); pa[mt][nt][1] = e; sA += e;
                    e = __expf(pa[mt][nt][2] - mxB); pa[mt][nt][2] = e; sB += e;
                    e = __expf(pa[mt][nt][3] - mxB); pa[mt][nt][3] = e; sB += e;
                }
                sA += __shfl_xor_sync(0xffffffffu, sA, 1);
                sA += __shfl_xor_sync(0xffffffffu, sA, 2);
                sB += __shfl_xor_sync(0xffffffffu, sB, 1);
                sB += __shfl_xor_sync(0xffffffffu, sB, 2);
                inv[mt][0] = 1.0f / sA;
                inv[mt][1] = 1.0f / sB;
            }

            // P @ V
            float xacc[2][2][4];
#pragma unroll
            for (int mt = 0; mt < 2; mt++)
#pragma unroll
                for (int n2 = 0; n2 < 2; n2++)
#pragma unroll
                    for (int i = 0; i < 4; i++) xacc[mt][n2][i] = 0.f;
#pragma unroll
            for (int mt = 0; mt < 2; mt++) {
#pragma unroll
                for (int kp = 0; kp < 4; kp++) {
                    uint32_t A[4];
                    A[0] = h2(pa[mt][2 * kp][0], pa[mt][2 * kp][1]);
                    A[1] = h2(pa[mt][2 * kp][2], pa[mt][2 * kp][3]);
                    A[2] = h2(pa[mt][2 * kp + 1][0], pa[mt][2 * kp + 1][1]);
                    A[3] = h2(pa[mt][2 * kp + 1][2], pa[mt][2 * kp + 1][3]);
                    uint4 V = lds128(smb + S_VP_B
                                     + (uint32_t)(tile * 16384 + ((h * 4 + kp) * 32 + lane) * 16));
                    mma16(xacc[mt][0], A, V.x, V.y);
                    mma16(xacc[mt][1], A, V.z, V.w);
                }
            }

            // x (normalized, fp16) -> S_IN tile rows
            int rowb = tile ? 70 : 2;
#pragma unroll
            for (int mt = 0; mt < 2; mt++) {
                int rA = mh + mt * 16 + r, rB = rA + 8;
                float iA = inv[mt][0], iB = inv[mt][1];
#pragma unroll
                for (int n2 = 0; n2 < 2; n2++) {
                    int col = h * 16 + n2 * 8 + 2 * c;
                    *(uint32_t*)(smc + S_IN_B + (rowb + rA) * 272 + col * 2) =
                        h2(xacc[mt][n2][0] * iA, xacc[mt][n2][1] * iA);
                    *(uint32_t*)(smc + S_IN_B + (rowb + rB) * 272 + col * 2) =
                        h2(xacc[mt][n2][2] * iB, xacc[mt][n2][3] * iB);
                }
            }
        }
    }
    __syncthreads();

    // ---- iter7: output projection (buf1 = Wo, pre-staged) ----
    zacc(acc);
    mma_chunk(acc, a_thr + 2 * 272, b_buf1);
    epi_g(out + base, bo, acc, lane, mg, ng);
}

extern "C" void kernel_launch(void* const* d_in, const int* in_sizes, int n_in,
                              void* d_out, int out_size) {
    (void)in_sizes; (void)n_in; (void)out_size;
    const float* query = (const float*)d_in[0];
    const float* key   = (const float*)d_in[1];
    const float* value = (const float*)d_in[2];
    const int*   mask  = (const int*)d_in[3];
    const float* Wq = (const float*)d_in[4];
    const float* bq = (const float*)d_in[5];
    const float* Wk = (const float*)d_in[6];
    const float* bk = (const float*)d_in[7];
    const float* Wv = (const float*)d_in[8];
    const float* bv = (const float*)d_in[9];
    const float* Wo = (const float*)d_in[10];
    const float* bo = (const float*)d_in[11];
    float* out = (float*)d_out;

    cudaFuncSetAttribute(attn_kernel, cudaFuncAttributeMaxDynamicSharedMemorySize, SMEM_BYTES);
    prep_kernel<<<64, 256>>>(Wq, Wk, Wv, Wo);
    attn_kernel<<<2048, 512, SMEM_BYTES>>>(query, key, value, mask, bq, bk, bv, bo, out);
}

// round 11
// speedup vs baseline: 1.0849x; 1.0849x over previous
#include <cuda_runtime.h>
#include <cuda_fp16.h>
#include <cstdint>

// B=8, N=512, T=64, D=128, H=8, DK=16, K=3.
// TWO (b,n) tiles per CTA (M=128), 512 thr = 16 warps, warp tile 32x32.
// fp16 MMA operands, fp32 accumulate. R11: cp.async double-buffered weight staging.

// byte offsets in dynamic smem
#define S_IN_B   0          // 136 rows x 272B fp16. pad rows 0,1,66-69,134,135 zero.
#define S_ST_B   36992      // 2 x 32KB double-buffered packed-B chunk
#define S_QP_B   102528     // 128 x 272B fp16 q tile
#define S_KP_B   137344     // 2 x 16KB packed K^T B-frags
#define S_VP_B   170112     // 2 x 16KB packed V B-frags
#define S_MSK_B  202880     // 64 x ull row masks
#define SMEM_BYTES 203392

// g_pack chunk offsets (uint32 units; each chunk = 8192 uint32 = 32KB)
#define PQ4 0
#define PK4 24576
#define PV4 49152
#define PO4 57344

typedef unsigned long long ull;
__device__ uint32_t g_pack[65536];

// ---------------- PTX helpers ----------------
__device__ __forceinline__ uint32_t smem_u32(const void* p) {
    uint32_t a;
    asm("{ .reg .u64 t; cvta.to.shared.u64 t, %1; cvt.u32.u64 %0, t; }" : "=r"(a) : "l"(p));
    return a;
}
__device__ __forceinline__ uint32_t h2(float lo, float hi) {
    uint32_t r; asm("cvt.rn.f16x2.f32 %0, %1, %2;" : "=r"(r) : "f"(hi), "f"(lo)); return r;
}
__device__ __forceinline__ uint4 lds128(uint32_t a) {
    uint4 v;
    asm volatile("ld.shared.v4.b32 {%0,%1,%2,%3}, [%4];"
                 : "=r"(v.x), "=r"(v.y), "=r"(v.z), "=r"(v.w) : "r"(a));
    return v;
}
__device__ __forceinline__ void ldsm4(uint32_t (&r)[4], uint32_t a) {
    asm volatile("ldmatrix.sync.aligned.m8n8.x4.shared.b16 {%0,%1,%2,%3}, [%4];"
                 : "=r"(r[0]), "=r"(r[1]), "=r"(r[2]), "=r"(r[3]) : "r"(a));
}
__device__ __forceinline__ void mma16(float (&c)[4], const uint32_t (&a)[4],
                                      uint32_t b0, uint32_t b1) {
    asm volatile(
        "mma.sync.aligned.m16n8k16.row.col.f32.f16.f16.f32 "
        "{%0,%1,%2,%3},{%4,%5,%6,%7},{%8,%9},{%0,%1,%2,%3};"
        : "+f"(c[0]), "+f"(c[1]), "+f"(c[2]), "+f"(c[3])
        : "r"(a[0]), "r"(a[1]), "r"(a[2]), "r"(a[3]), "r"(b0), "r"(b1));
}
// register-free global->shared prefetch of one 32KB weight chunk
__device__ __forceinline__ void cpasyncB(uint32_t smb, int buf,
                                         const uint4* __restrict__ g4, int tid) {
#pragma unroll
    for (int r = 0; r < 4; r++) {
        uint32_t dst = smb + S_ST_B + (uint32_t)(buf * 32768 + (tid + r * 512) * 16);
        asm volatile("cp.async.cg.shared.global [%0], [%1], 16;"
                     :: "r"(dst), "l"(g4 + tid + r * 512) : "memory");
    }
    asm volatile("cp.async.commit_group;" ::: "memory");
}
#define CP_WAIT0() asm volatile("cp.async.wait_group 0;" ::: "memory")

// ---------------- prep: pack weights as fp16 B-fragments ----------------
__global__ void prep_kernel(const float* __restrict__ Wq, const float* __restrict__ Wk,
                            const float* __restrict__ Wv, const float* __restrict__ Wo) {
    int idx = blockIdx.x * blockDim.x + threadIdx.x;   // 16384
    if (idx >= 16384) return;
    const float* W; int base4, within, j = 0, conv; float sc = 1.0f;
    if (idx < 6144)       { W = Wq; j = idx >> 11; within = idx & 2047; base4 = PQ4 / 4 + idx; conv = 1; sc = 0.25f; }
    else if (idx < 12288) { int i2 = idx - 6144; W = Wk; j = i2 >> 11; within = i2 & 2047; base4 = PK4 / 4 + i2; conv = 1; }
    else if (idx < 14336) { int i2 = idx - 12288; W = Wv; within = i2; base4 = PV4 / 4 + i2; conv = 0; }
    else                  { int i2 = idx - 14336; W = Wo; within = i2; base4 = PO4 / 4 + i2; conv = 0; }
    int lane = within & 31, njp = (within >> 5) & 7, ksp = within >> 8;
    int n0 = njp * 16 + (lane >> 2);
    int n1 = n0 + 8;
    int k0 = ksp * 16 + 2 * (lane & 3);
    float w[8];
    if (conv) {
        w[0] = W[(n0 * 128 + k0) * 3 + j];     w[1] = W[(n0 * 128 + k0 + 1) * 3 + j];
        w[2] = W[(n0 * 128 + k0 + 8) * 3 + j]; w[3] = W[(n0 * 128 + k0 + 9) * 3 + j];
        w[4] = W[(n1 * 128 + k0) * 3 + j];     w[5] = W[(n1 * 128 + k0 + 1) * 3 + j];
        w[6] = W[(n1 * 128 + k0 + 8) * 3 + j]; w[7] = W[(n1 * 128 + k0 + 9) * 3 + j];
    } else {
        w[0] = W[n0 * 128 + k0];     w[1] = W[n0 * 128 + k0 + 1];
        w[2] = W[n0 * 128 + k0 + 8]; w[3] = W[n0 * 128 + k0 + 9];
        w[4] = W[n1 * 128 + k0];     w[5] = W[n1 * 128 + k0 + 1];
        w[6] = W[n1 * 128 + k0 + 8]; w[7] = W[n1 * 128 + k0 + 9];
    }
    uint4 o;
    o.x = h2(w[0] * sc, w[1] * sc);
    o.y = h2(w[2] * sc, w[3] * sc);
    o.z = h2(w[4] * sc, w[5] * sc);
    o.w = h2(w[6] * sc, w[7] * sc);
    ((uint4*)g_pack)[base4] = o;
}

// ---------------- building blocks ----------------
__device__ __forceinline__ void load_input(char* smc, const float* __restrict__ g, int tid) {
#pragma unroll
    for (int r = 0; r < 8; r++) {
        int idx = tid + r * 512;                       // 4096 float4 (2 tiles)
        float4 f = *(const float4*)(g + idx * 4);
        int tile = idx >> 11, within = idx & 2047;
        int t = within >> 5, d = (within & 31) * 4;
        int row = (tile ? 70 : 2) + t;
        uint2 v;
        v.x = h2(f.x, f.y);
        v.y = h2(f.z, f.w);
        *(uint2*)(smc + S_IN_B + row * 272 + d * 2) = v;
    }
}
// one K=128 chunk, warp tile 32x32
__device__ __forceinline__ void mma_chunk(float (&acc)[2][4][4], uint32_t a0, uint32_t b0) {
#pragma unroll
    for (int ksp = 0; ksp < 8; ksp++) {
        uint32_t A0[4], A1[4];
        ldsm4(A0, a0 + ksp * 32);
        ldsm4(A1, a0 + 16 * 272 + ksp * 32);
        uint4 B01 = lds128(b0 + ksp * 4096);
        uint4 B23 = lds128(b0 + ksp * 4096 + 512);
        mma16(acc[0][0], A0, B01.x, B01.y);
        mma16(acc[0][1], A0, B01.z, B01.w);
        mma16(acc[0][2], A0, B23.x, B23.y);
        mma16(acc[0][3], A0, B23.z, B23.w);
        mma16(acc[1][0], A1, B01.x, B01.y);
        mma16(acc[1][1], A1, B01.z, B01.w);
        mma16(acc[1][2], A1, B23.x, B23.y);
        mma16(acc[1][3], A1, B23.z, B23.w);
    }
}
__device__ __forceinline__ void zacc(float (&acc)[2][4][4]) {
#pragma unroll
    for (int s = 0; s < 2; s++)
#pragma unroll
        for (int i = 0; i < 4; i++)
#pragma unroll
            for (int k = 0; k < 4; k++) acc[s][i][k] = 0.f;
}
// ---------------- epilogues (same layouts as R9) ----------------
__device__ __forceinline__ void epi_q(char* smc, const float* __restrict__ bq,
                                      float (&acc)[2][4][4], int lane, int mg, int ng) {
#pragma unroll
    for (int msub = 0; msub < 2; msub++) {
        int r0 = mg * 32 + msub * 16 + (lane >> 2);
#pragma unroll
        for (int nt = 0; nt < 4; nt++) {
            int col = ng * 32 + nt * 8 + (lane & 3) * 2;
            float2 bb = *(const float2*)(bq + col);
            *(uint32_t*)(smc + S_QP_B + r0 * 272 + col * 2) =
                h2(acc[msub][nt][0] + bb.x * 0.25f, acc[msub][nt][1] + bb.y * 0.25f);
            *(uint32_t*)(smc + S_QP_B + (r0 + 8) * 272 + col * 2) =
                h2(acc[msub][nt][2] + bb.x * 0.25f, acc[msub][nt][3] + bb.y * 0.25f);
        }
    }
}
__device__ __forceinline__ void epi_k(char* smc, const float* __restrict__ bk,
                                      float (&acc)[2][4][4], int lane, int mg, int ng) {
#pragma unroll
    for (int msub = 0; msub < 2; msub++) {
#pragma unroll
        for (int nt = 0; nt < 4; nt++) {
#pragma unroll
            for (int i = 0; i < 4; i++) {
                int s = mg * 32 + msub * 16 + (lane >> 2) + (i >> 1) * 8;
                int col = ng * 32 + nt * 8 + (lane & 3) * 2 + (i & 1);
                int tile = s >> 6, st = s & 63;
                int h = col >> 4, dk = col & 15;
                int ntb = st >> 3, ntp = ntb >> 1;
                int lp = ((st & 7) << 2) | ((dk >> 1) & 3);
                int off = tile * 16384 + ((h * 4 + ntp) * 32 + lp) * 16
                        + (ntb & 1) * 8 + (dk >> 3) * 4 + (dk & 1) * 2;
                *(__half*)(smc + S_KP_B + off) =
                    __float2half_rn(acc[msub][nt][i] + __ldg(bk + col));
            }
        }
    }
}
__device__ __forceinline__ void epi_v(char* smc, const float* __restrict__ bv,
                                      float (&acc)[2][4][4], int lane, int mg, int ng) {
#pragma unroll
    for (int msub = 0; msub < 2; msub++) {
#pragma unroll
        for (int nt = 0; nt < 4; nt++) {
#pragma unroll
            for (int i = 0; i < 4; i++) {
                int s = mg * 32 + msub * 16 + (lane >> 2) + (i >> 1) * 8;
                int col = ng * 32 + nt * 8 + (lane & 3) * 2 + (i & 1);
                int tile = s >> 6, st = s & 63;
                int h = col >> 4, dk = col & 15;
                int ksp = st >> 4, ntv = dk >> 3;
                int lp = ((dk & 7) << 2) | ((st >> 1) & 3);
                int off = tile * 16384 + ((h * 4 + ksp) * 32 + lp) * 16
                        + ntv * 8 + ((st >> 3) & 1) * 4 + (st & 1) * 2;
                *(__half*)(smc + S_VP_B + off) =
                    __float2half_rn(acc[msub][nt][i] + __ldg(bv + col));
            }
        }
    }
}
__device__ __forceinline__ void epi_g(float* __restrict__ dst, const float* __restrict__ bias,
                                      float (&acc)[2][4][4], int lane, int mg, int ng) {
#pragma unroll
    for (int msub = 0; msub < 2; msub++) {
        int r0 = mg * 32 + msub * 16 + (lane >> 2);
#pragma unroll
        for (int nt = 0; nt < 4; nt++) {
            int col = ng * 32 + nt * 8 + (lane & 3) * 2;
            float2 bb = *(const float2*)(bias + col);
            float* d0 = dst + (r0 >> 6) * 8192 + (r0 & 63) * 128 + col;
            float* d1 = dst + ((r0 + 8) >> 6) * 8192 + ((r0 + 8) & 63) * 128 + col;
            *(float2*)d0 = make_float2(acc[msub][nt][0] + bb.x, acc[msub][nt][1] + bb.y);
            *(float2*)d1 = make_float2(acc[msub][nt][2] + bb.x, acc[msub][nt][3] + bb.y);
        }
    }
}

__global__ void __launch_bounds__(512, 1)
attn_kernel(const float* __restrict__ query, const float* __restrict__ key,
            const float* __restrict__ value, const int* __restrict__ mask,
            const float* __restrict__ bq, const float* __restrict__ bk,
            const float* __restrict__ bv, const float* __restrict__ bo,
            float* __restrict__ out)
{
    extern __shared__ char smc[];
    uint32_t smb = smem_u32(smc);
    const int tid = threadIdx.x, lane = tid & 31, wid = tid >> 5;
    const int cta = blockIdx.x, b = cta >> 8;
    const long long base = (long long)cta * 16384;

    const int mg = wid >> 2, ng = wid & 3;
    const int rowbase = (mg & 1) * 32 + (lane & 15) + ((mg >> 1) ? 68 : 0);
    const uint32_t a_thr = smb + S_IN_B + (uint32_t)(rowbase * 272 + (lane >> 4) * 16);
    const uint32_t b_lane_off = (uint32_t)((ng * 64 + lane) * 16);
    const uint32_t b_buf0 = smb + S_ST_B + b_lane_off;
    const uint32_t b_buf1 = smb + S_ST_B + 32768u + b_lane_off;

    // ---- prologue ----
    cpasyncB(smb, 0, (const uint4*)(g_pack + PV4), tid);   // chunk0 -> buf0
    if (tid < 544) {
        int rr = tid / 68, off = tid - rr * 68;
        int row = (rr < 2) ? rr : ((rr < 6) ? (64 + rr) : (128 + rr));
        *(uint32_t*)(smc + S_IN_B + row * 272 + off * 4) = 0u;
    }
    if (tid < 64) {
        ull m = 0;
        const int4* mr = (const int4*)(mask + b * 4096 + tid * 64);
#pragma unroll
        for (int u = 0; u < 16; u++) {
            int4 mm = mr[u];
            ull bits = (ull)(mm.x != 0) | ((ull)(mm.y != 0) << 1) |
                       ((ull)(mm.z != 0) << 2) | ((ull)(mm.w != 0) << 3);
            m |= bits << (u * 4);
        }
        *(ull*)(smc + S_MSK_B + tid * 8) = m;
    }
    load_input(smc, value + base, tid);
    CP_WAIT0();
    __syncthreads();

    float acc[2][4][4];

    // ---- iter0: v GEMM (buf0); prefetch PQ0 -> buf1 ----
    cpasyncB(smb, 1, (const uint4*)(g_pack + PQ4), tid);
    zacc(acc);
    mma_chunk(acc, a_thr + 2 * 272, b_buf0);
    epi_v(smc, bv, acc, lane, mg, ng);
    __syncthreads();                      // S_IN(value) reads done
    load_input(smc, query + base, tid);   // query in
    CP_WAIT0();
    __syncthreads();

    // ---- iter1: q tap0 (buf1); prefetch PQ1 -> buf0 ----
    cpasyncB(smb, 0, (const uint4*)(g_pack + PQ4 + 8192), tid);
    zacc(acc);
    mma_chunk(acc, a_thr + 0 * 272, b_buf1);
    CP_WAIT0();
    __syncthreads();

    // ---- iter2: q tap1 (buf0); prefetch PQ2 -> buf1 ----
    cpasyncB(smb, 1, (const uint4*)(g_pack + PQ4 + 16384), tid);
    mma_chunk(acc, a_thr + 1 * 272, b_buf0);
    CP_WAIT0();
    __syncthreads();

    // ---- iter3: q tap2 (buf1); prefetch PK0 -> buf0 ----
    cpasyncB(smb, 0, (const uint4*)(g_pack + PK4), tid);
    mma_chunk(acc, a_thr + 2 * 272, b_buf1);
    epi_q(smc, bq, acc, lane, mg, ng);
    __syncthreads();                      // S_IN(query) reads done
    load_input(smc, key + base, tid);     // key in
    CP_WAIT0();
    __syncthreads();

    // ---- iter4: k tap1 (buf0); prefetch PK1 -> buf1 ----
    cpasyncB(smb, 1, (const uint4*)(g_pack + PK4 + 8192), tid);
    zacc(acc);
    mma_chunk(acc, a_thr + 1 * 272, b_buf0);
    CP_WAIT0();
    __syncthreads();

    // ---- iter5: k tap2 (buf1); prefetch PK2 -> buf0 ----
    cpasyncB(smb, 0, (const uint4*)(g_pack + PK4 + 16384), tid);
    mma_chunk(acc, a_thr + 2 * 272, b_buf1);
    CP_WAIT0();
    __syncthreads();

    // ---- iter6: k tap3 (buf0); prefetch PO -> buf1 ----
    cpasyncB(smb, 1, (const uint4*)(g_pack + PO4), tid);
    mma_chunk(acc, a_thr + 3 * 272, b_buf0);
    epi_k(smc, bk, acc, lane, mg, ng);
    CP_WAIT0();
    __syncthreads();                      // KP/QP/VP + Wo visible

    // ---- attention: warp -> head (wid>>1), row half (wid&1)*32, both tiles ----
    {
        const int h = wid >> 1;
        const int mh = (wid & 1) * 32;
        const int r = lane >> 2, c = lane & 3;
#pragma unroll 1
        for (int tile = 0; tile < 2; tile++) {
            float pa[2][8][4];
#pragma unroll
            for (int mt = 0; mt < 2; mt++)
#pragma unroll
                for (int nt = 0; nt < 8; nt++)
#pragma unroll
                    for (int i = 0; i < 4; i++) pa[mt][nt][i] = 0.f;

            // QK^T
#pragma unroll
            for (int mt = 0; mt < 2; mt++) {
                uint32_t A[4];
                ldsm4(A, smb + S_QP_B
                         + (uint32_t)((tile * 64 + mh + mt * 16 + (lane & 15)) * 272
                                      + h * 32 + (lane >> 4) * 16));
#pragma unroll
                for (int ntp = 0; ntp < 4; ntp++) {
                    uint4 Bf = lds128(smb + S_KP_B
                                      + (uint32_t)(tile * 16384 + ((h * 4 + ntp) * 32 + lane) * 16));
                    mma16(pa[mt][2 * ntp], A, Bf.x, Bf.y);
                    mma16(pa[mt][2 * ntp + 1], A, Bf.z, Bf.w);
                }
            }

            // masked softmax
            float inv[2][2];
#pragma unroll
            for (int mt = 0; mt < 2; mt++) {
                ull mA = *(const ull*)(smc + S_MSK_B + (mh + mt * 16 + r) * 8);
                ull mB = *(const ull*)(smc + S_MSK_B + (mh + mt * 16 + r + 8) * 8);
                float mxA = -3.0e38f, mxB = -3.0e38f;
#pragma unroll
                for (int nt = 0; nt < 8; nt++) {
                    int c0 = nt * 8 + 2 * c, c1 = c0 + 1;
                    float v;
                    v = ((mA >> c0) & 1) ? pa[mt][nt][0] : -1.0e9f; pa[mt][nt][0] = v; mxA = fmaxf(mxA, v);
                    v = ((mA >> c1) & 1) ? pa[mt][nt][1] : -1.0e9f; pa[mt][nt][1] = v; mxA = fmaxf(mxA, v);
                    v = ((mB >> c0) & 1) ? pa[mt][nt][2] : -1.0e9f; pa[mt][nt][2] = v; mxB = fmaxf(mxB, v);
                    v = ((mB >> c1) & 1) ? pa[mt][nt][3] : -1.0e9f; pa[mt][nt][3] = v; mxB = fmaxf(mxB, v);
                }
                mxA = fmaxf(mxA, __shfl_xor_sync(0xffffffffu, mxA, 1));
                mxA = fmaxf(mxA, __shfl_xor_sync(0xffffffffu, mxA, 2));
                mxB = fmaxf(mxB, __shfl_xor_sync(0xffffffffu, mxB, 1));
                mxB = fmaxf(mxB, __shfl_xor_sync(0xffffffffu, mxB, 2));
                float sA = 0.f, sB = 0.f;
#pragma unroll
                for (int nt = 0; nt < 8; nt++) {
                    float e;
                    e = __expf(pa[mt][nt][0] - mxA); pa[mt][nt][0] = e; sA += e;
                    e = __expf(pa[mt][nt][1] - mxA); pa[mt][nt][1] = e; sA += e;
                    e = __expf(pa[mt][nt][2] - mxB); pa[mt][nt][2] = e; sB += e;
                    e = __expf(pa[mt][nt][3] - mxB); pa[mt][nt][3] = e; sB += e;
                }
                sA += __shfl_xor_sync(0xffffffffu, sA, 1);
                sA += __shfl_xor_sync(0xffffffffu, sA, 2);
                sB += __shfl_xor_sync(0xffffffffu, sB, 1);
                sB += __shfl_xor_sync(0xffffffffu, sB, 2);
                inv[mt][0] = 1.0f / sA;
                inv[mt][1] = 1.0f / sB;
            }

            // P @ V
            float xacc[2][2][4];
#pragma unroll
            for (int mt = 0; mt < 2; mt++)
#pragma unroll
                for (int n2 = 0; n2 < 2; n2++)
#pragma unroll
                    for (int i = 0; i < 4; i++) xacc[mt][n2][i] = 0.f;
#pragma unroll
            for (int mt = 0; mt < 2; mt++) {
#pragma unroll
                for (int kp = 0; kp < 4; kp++) {
                    uint32_t A[4];
                    A[0] = h2(pa[mt][2 * kp][0], pa[mt][2 * kp][1]);
                    A[1] = h2(pa[mt][2 * kp][2], pa[mt][2 * kp][3]);
                    A[2] = h2(pa[mt][2 * kp + 1][0], pa[mt][2 * kp + 1][1]);
                    A[3] = h2(pa[mt][2 * kp + 1][2], pa[mt][2 * kp + 1][3]);
                    uint4 V = lds128(smb + S_VP_B
                                     + (uint32_t)(tile * 16384 + ((h * 4 + kp) * 32 + lane) * 16));
                    mma16(xacc[mt][0], A, V.x, V.y);
                    mma16(xacc[mt][1], A, V.z, V.w);
                }
            }

            // x (normalized, fp16) -> S_IN tile rows
            int rowb = tile ? 70 : 2;
#pragma unroll
            for (int mt = 0; mt < 2; mt++) {
                int rA = mh + mt * 16 + r, rB = rA + 8;
                float iA = inv[mt][0], iB = inv[mt][1];
#pragma unroll
                for (int n2 = 0; n2 < 2; n2++) {
                    int col = h * 16 + n2 * 8 + 2 * c;
                    *(uint32_t*)(smc + S_IN_B + (rowb + rA) * 272 + col * 2) =
                        h2(xacc[mt][n2][0] * iA, xacc[mt][n2][1] * iA);
                    *(uint32_t*)(smc + S_IN_B + (rowb + rB) * 272 + col * 2) =
                        h2(xacc[mt][n2][2] * iB, xacc[mt][n2][3] * iB);
                }
            }
        }
    }
    __syncthreads();

    // ---- iter7: output projection (buf1 = Wo, pre-staged) ----
    zacc(acc);
    mma_chunk(acc, a_thr + 2 * 272, b_buf1);
    epi_g(out + base, bo, acc, lane, mg, ng);
}

extern "C" void kernel_launch(void* const* d_in, const int* in_sizes, int n_in,
                              void* d_out, int out_size) {
    (void)in_sizes; (void)n_in; (void)out_size;
    const float* query = (const float*)d_in[0];
    const float* key   = (const float*)d_in[1];
    const float* value = (const float*)d_in[2];
    const int*   mask  = (const int*)d_in[3];
    const float* Wq = (const float*)d_in[4];
    const float* bq = (const float*)d_in[5];
    const float* Wk = (const float*)d_in[6];
    const float* bk = (const float*)d_in[7];
    const float* Wv = (const float*)d_in[8];
    const float* bv = (const float*)d_in[9];
    const float* Wo = (const float*)d_in[10];
    const float* bo = (const float*)d_in[11];
    float* out = (float*)d_out;

    cudaFuncSetAttribute(attn_kernel, cudaFuncAttributeMaxDynamicSharedMemorySize, SMEM_BYTES);
    prep_kernel<<<64, 256>>>(Wq, Wk, Wv, Wo);
    attn_kernel<<<2048, 512, SMEM_BYTES>>>(query, key, value, mask, bq, bk, bv, bo, out);
}

// round 12
// speedup vs baseline: 1.1336x; 1.0449x over previous
#include <cuda_runtime.h>
#include <cuda_fp16.h>
#include <cstdint>

// B=8, N=512, T=64, D=128, H=8, DK=16, K=3.
// R12: ONE (b,n) tile per CTA (M=64), 256 thr = 8 warps, warp tile 32x32,
// 2 CTAs/SM (occ 50%). fp16 MMA operands, fp32 accumulate.

// byte offsets in dynamic smem (per CTA ~99.6KB)
#define S_IN_B   0          // 68 rows x 272B fp16 (rows 0,1,66,67 zero pad)
#define S_ST_B   18496      // 32KB single-buffered packed-B chunk
#define S_QP_B   51264      // 64 x 272B fp16 q tile
#define S_KP_B   68672      // 16KB packed K^T B-frags
#define S_VP_B   85056      // 16KB packed V B-frags
#define S_MSK_B  101440     // 64 x ull row masks
#define SMEM_BYTES 101952

// g_pack chunk offsets (uint32 units; each chunk = 8192 uint32 = 32KB)
#define PQ4 0
#define PK4 24576
#define PV4 49152
#define PO4 57344

typedef unsigned long long ull;
__device__ uint32_t g_pack[65536];

// ---------------- PTX helpers ----------------
__device__ __forceinline__ uint32_t smem_u32(const void* p) {
    uint32_t a;
    asm("{ .reg .u64 t; cvta.to.shared.u64 t, %1; cvt.u32.u64 %0, t; }" : "=r"(a) : "l"(p));
    return a;
}
__device__ __forceinline__ uint32_t h2(float lo, float hi) {
    uint32_t r; asm("cvt.rn.f16x2.f32 %0, %1, %2;" : "=r"(r) : "f"(hi), "f"(lo)); return r;
}
__device__ __forceinline__ uint4 lds128(uint32_t a) {
    uint4 v;
    asm volatile("ld.shared.v4.b32 {%0,%1,%2,%3}, [%4];"
                 : "=r"(v.x), "=r"(v.y), "=r"(v.z), "=r"(v.w) : "r"(a));
    return v;
}
__device__ __forceinline__ void ldsm4(uint32_t (&r)[4], uint32_t a) {
    asm volatile("ldmatrix.sync.aligned.m8n8.x4.shared.b16 {%0,%1,%2,%3}, [%4];"
                 : "=r"(r[0]), "=r"(r[1]), "=r"(r[2]), "=r"(r[3]) : "r"(a));
}
__device__ __forceinline__ void mma16(float (&c)[4], const uint32_t (&a)[4],
                                      uint32_t b0, uint32_t b1) {
    asm volatile(
        "mma.sync.aligned.m16n8k16.row.col.f32.f16.f16.f32 "
        "{%0,%1,%2,%3},{%4,%5,%6,%7},{%8,%9},{%0,%1,%2,%3};"
        : "+f"(c[0]), "+f"(c[1]), "+f"(c[2]), "+f"(c[3])
        : "r"(a[0]), "r"(a[1]), "r"(a[2]), "r"(a[3]), "r"(b0), "r"(b1));
}
// register-free global->shared prefetch of one 32KB weight chunk (256 thr: 8 ops)
__device__ __forceinline__ void cpasyncB(uint32_t smb, const uint4* __restrict__ g4, int tid) {
#pragma unroll
    for (int r = 0; r < 8; r++) {
        uint32_t dst = smb + S_ST_B + (uint32_t)((tid + r * 256) * 16);
        asm volatile("cp.async.cg.shared.global [%0], [%1], 16;"
                     :: "r"(dst), "l"(g4 + tid + r * 256) : "memory");
    }
    asm volatile("cp.async.commit_group;" ::: "memory");
}
#define CP_WAIT0() asm volatile("cp.async.wait_group 0;" ::: "memory")

// ---------------- prep: pack weights as fp16 B-fragments (unchanged) ----------------
__global__ void prep_kernel(const float* __restrict__ Wq, const float* __restrict__ Wk,
                            const float* __restrict__ Wv, const float* __restrict__ Wo) {
    int idx = blockIdx.x * blockDim.x + threadIdx.x;   // 16384
    if (idx >= 16384) return;
    const float* W; int base4, within, j = 0, conv; float sc = 1.0f;
    if (idx < 6144)       { W = Wq; j = idx >> 11; within = idx & 2047; base4 = PQ4 / 4 + idx; conv = 1; sc = 0.25f; }
    else if (idx < 12288) { int i2 = idx - 6144; W = Wk; j = i2 >> 11; within = i2 & 2047; base4 = PK4 / 4 + i2; conv = 1; }
    else if (idx < 14336) { int i2 = idx - 12288; W = Wv; within = i2; base4 = PV4 / 4 + i2; conv = 0; }
    else                  { int i2 = idx - 14336; W = Wo; within = i2; base4 = PO4 / 4 + i2; conv = 0; }
    int lane = within & 31, njp = (within >> 5) & 7, ksp = within >> 8;
    int n0 = njp * 16 + (lane >> 2);
    int n1 = n0 + 8;
    int k0 = ksp * 16 + 2 * (lane & 3);
    float w[8];
    if (conv) {
        w[0] = W[(n0 * 128 + k0) * 3 + j];     w[1] = W[(n0 * 128 + k0 + 1) * 3 + j];
        w[2] = W[(n0 * 128 + k0 + 8) * 3 + j]; w[3] = W[(n0 * 128 + k0 + 9) * 3 + j];
        w[4] = W[(n1 * 128 + k0) * 3 + j];     w[5] = W[(n1 * 128 + k0 + 1) * 3 + j];
        w[6] = W[(n1 * 128 + k0 + 8) * 3 + j]; w[7] = W[(n1 * 128 + k0 + 9) * 3 + j];
    } else {
        w[0] = W[n0 * 128 + k0];     w[1] = W[n0 * 128 + k0 + 1];
        w[2] = W[n0 * 128 + k0 + 8]; w[3] = W[n0 * 128 + k0 + 9];
        w[4] = W[n1 * 128 + k0];     w[5] = W[n1 * 128 + k0 + 1];
        w[6] = W[n1 * 128 + k0 + 8]; w[7] = W[n1 * 128 + k0 + 9];
    }
    uint4 o;
    o.x = h2(w[0] * sc, w[1] * sc);
    o.y = h2(w[2] * sc, w[3] * sc);
    o.z = h2(w[4] * sc, w[5] * sc);
    o.w = h2(w[6] * sc, w[7] * sc);
    ((uint4*)g_pack)[base4] = o;
}

// ---------------- building blocks ----------------
__device__ __forceinline__ void load_input(char* smc, const float* __restrict__ g, int tid) {
#pragma unroll
    for (int r = 0; r < 8; r++) {
        int idx = tid + r * 256;                       // 2048 float4 (1 tile)
        float4 f = *(const float4*)(g + idx * 4);
        int t = idx >> 5, d = (idx & 31) * 4;
        uint2 v;
        v.x = h2(f.x, f.y);
        v.y = h2(f.z, f.w);
        *(uint2*)(smc + S_IN_B + (t + 2) * 272 + d * 2) = v;
    }
}
// one K=128 chunk, warp tile 32x32
__device__ __forceinline__ void mma_chunk(float (&acc)[2][4][4], uint32_t a0, uint32_t b0) {
#pragma unroll
    for (int ksp = 0; ksp < 8; ksp++) {
        uint32_t A0[4], A1[4];
        ldsm4(A0, a0 + ksp * 32);
        ldsm4(A1, a0 + 16 * 272 + ksp * 32);
        uint4 B01 = lds128(b0 + ksp * 4096);
        uint4 B23 = lds128(b0 + ksp * 4096 + 512);
        mma16(acc[0][0], A0, B01.x, B01.y);
        mma16(acc[0][1], A0, B01.z, B01.w);
        mma16(acc[0][2], A0, B23.x, B23.y);
        mma16(acc[0][3], A0, B23.z, B23.w);
        mma16(acc[1][0], A1, B01.x, B01.y);
        mma16(acc[1][1], A1, B01.z, B01.w);
        mma16(acc[1][2], A1, B23.x, B23.y);
        mma16(acc[1][3], A1, B23.z, B23.w);
    }
}
__device__ __forceinline__ void zacc(float (&acc)[2][4][4]) {
#pragma unroll
    for (int s = 0; s < 2; s++)
#pragma unroll
        for (int i = 0; i < 4; i++)
#pragma unroll
            for (int k = 0; k < 4; k++) acc[s][i][k] = 0.f;
}
// ---------------- epilogues (R9 layouts, single tile: s in 0..63) ----------------
__device__ __forceinline__ void epi_q(char* smc, const float* __restrict__ bq,
                                      float (&acc)[2][4][4], int lane, int mg, int ng) {
#pragma unroll
    for (int msub = 0; msub < 2; msub++) {
        int r0 = mg * 32 + msub * 16 + (lane >> 2);
#pragma unroll
        for (int nt = 0; nt < 4; nt++) {
            int col = ng * 32 + nt * 8 + (lane & 3) * 2;
            float2 bb = *(const float2*)(bq + col);
            *(uint32_t*)(smc + S_QP_B + r0 * 272 + col * 2) =
                h2(acc[msub][nt][0] + bb.x * 0.25f, acc[msub][nt][1] + bb.y * 0.25f);
            *(uint32_t*)(smc + S_QP_B + (r0 + 8) * 272 + col * 2) =
                h2(acc[msub][nt][2] + bb.x * 0.25f, acc[msub][nt][3] + bb.y * 0.25f);
        }
    }
}
__device__ __forceinline__ void epi_k(char* smc, const float* __restrict__ bk,
                                      float (&acc)[2][4][4], int lane, int mg, int ng) {
#pragma unroll
    for (int msub = 0; msub < 2; msub++) {
#pragma unroll
        for (int nt = 0; nt < 4; nt++) {
#pragma unroll
            for (int i = 0; i < 4; i++) {
                int s = mg * 32 + msub * 16 + (lane >> 2) + (i >> 1) * 8;
                int col = ng * 32 + nt * 8 + (lane & 3) * 2 + (i & 1);
                int h = col >> 4, dk = col & 15;
                int ntb = s >> 3, ntp = ntb >> 1;
                int lp = ((s & 7) << 2) | ((dk >> 1) & 3);
                int off = ((h * 4 + ntp) * 32 + lp) * 16
                        + (ntb & 1) * 8 + (dk >> 3) * 4 + (dk & 1) * 2;
                *(__half*)(smc + S_KP_B + off) =
                    __float2half_rn(acc[msub][nt][i] + __ldg(bk + col));
            }
        }
    }
}
__device__ __forceinline__ void epi_v(char* smc, const float* __restrict__ bv,
                                      float (&acc)[2][4][4], int lane, int mg, int ng) {
#pragma unroll
    for (int msub = 0; msub < 2; msub++) {
#pragma unroll
        for (int nt = 0; nt < 4; nt++) {
#pragma unroll
            for (int i = 0; i < 4; i++) {
                int s = mg * 32 + msub * 16 + (lane >> 2) + (i >> 1) * 8;
                int col = ng * 32 + nt * 8 + (lane & 3) * 2 + (i & 1);
                int h = col >> 4, dk = col & 15;
                int ksp = s >> 4, ntv = dk >> 3;
                int lp = ((dk & 7) << 2) | ((s >> 1) & 3);
                int off = ((h * 4 + ksp) * 32 + lp) * 16
                        + ntv * 8 + ((s >> 3) & 1) * 4 + (s & 1) * 2;
                *(__half*)(smc + S_VP_B + off) =
                    __float2half_rn(acc[msub][nt][i] + __ldg(bv + col));
            }
        }
    }
}
__device__ __forceinline__ void epi_g(float* __restrict__ dst, const float* __restrict__ bias,
                                      float (&acc)[2][4][4], int lane, int mg, int ng) {
#pragma unroll
    for (int msub = 0; msub < 2; msub++) {
        int r0 = mg * 32 + msub * 16 + (lane >> 2);
#pragma unroll
        for (int nt = 0; nt < 4; nt++) {
            int col = ng * 32 + nt * 8 + (lane & 3) * 2;
            float2 bb = *(const float2*)(bias + col);
            *(float2*)(dst + r0 * 128 + col) = make_float2(acc[msub][nt][0] + bb.x, acc[msub][nt][1] + bb.y);
            *(float2*)(dst + (r0 + 8) * 128 + col) = make_float2(acc[msub][nt][2] + bb.x, acc[msub][nt][3] + bb.y);
        }
    }
}

__global__ void __launch_bounds__(256, 2)
attn_kernel(const float* __restrict__ query, const float* __restrict__ key,
            const float* __restrict__ value, const int* __restrict__ mask,
            const float* __restrict__ bq, const float* __restrict__ bk,
            const float* __restrict__ bv, const float* __restrict__ bo,
            float* __restrict__ out)
{
    extern __shared__ char smc[];
    uint32_t smb = smem_u32(smc);
    const int tid = threadIdx.x, lane = tid & 31, wid = tid >> 5;
    const int cta = blockIdx.x, b = cta >> 9;
    const long long base = (long long)cta * 8192;

    const int mg = wid >> 2, ng = wid & 3;
    const int rowbase = mg * 32 + (lane & 15);
    const uint32_t a_thr = smb + S_IN_B + (uint32_t)(rowbase * 272 + (lane >> 4) * 16);
    const uint32_t b_thr = smb + S_ST_B + (uint32_t)((ng * 64 + lane) * 16);

    // ---- prologue ----
    cpasyncB(smb, (const uint4*)(g_pack + PV4), tid);
    if (tid < 136) {
        int rr = tid >> 5, off = tid & 31;          // covers 4 pad rows x 34 u64? no:
    }
    // zero pad rows 0,1,66,67: 4 rows x 272B = 1088B = 136 u64
    {
        int z = tid;
        if (z < 136) {
            int rr = z / 34, off = z - rr * 34;
            int row = (rr < 2) ? rr : (64 + rr);
            *(ull*)(smc + S_IN_B + row * 272 + off * 8) = 0ull;
        }
    }
    if (tid < 64) {
        ull m = 0;
        const int4* mr = (const int4*)(mask + b * 4096 + tid * 64);
#pragma unroll
        for (int u = 0; u < 16; u++) {
            int4 mm = mr[u];
            ull bits = (ull)(mm.x != 0) | ((ull)(mm.y != 0) << 1) |
                       ((ull)(mm.z != 0) << 2) | ((ull)(mm.w != 0) << 3);
            m |= bits << (u * 4);
        }
        *(ull*)(smc + S_MSK_B + tid * 8) = m;
    }
    load_input(smc, value + base, tid);
    CP_WAIT0();
    __syncthreads();

    float acc[2][4][4];

    // ---- iter0: v GEMM ----
    zacc(acc);
    mma_chunk(acc, a_thr + 2 * 272, b_thr);
    epi_v(smc, bv, acc, lane, mg, ng);
    __syncthreads();
    cpasyncB(smb, (const uint4*)(g_pack + PQ4), tid);
    load_input(smc, query + base, tid);
    CP_WAIT0();
    __syncthreads();

    // ---- iter1: q tap0 ----
    zacc(acc);
    mma_chunk(acc, a_thr + 0 * 272, b_thr);
    __syncthreads();
    cpasyncB(smb, (const uint4*)(g_pack + PQ4 + 8192), tid);
    CP_WAIT0();
    __syncthreads();

    // ---- iter2: q tap1 ----
    mma_chunk(acc, a_thr + 1 * 272, b_thr);
    __syncthreads();
    cpasyncB(smb, (const uint4*)(g_pack + PQ4 + 16384), tid);
    CP_WAIT0();
    __syncthreads();

    // ---- iter3: q tap2 ----
    mma_chunk(acc, a_thr + 2 * 272, b_thr);
    epi_q(smc, bq, acc, lane, mg, ng);
    __syncthreads();
    cpasyncB(smb, (const uint4*)(g_pack + PK4), tid);
    load_input(smc, key + base, tid);
    CP_WAIT0();
    __syncthreads();

    // ---- iter4: k tap1 ----
    zacc(acc);
    mma_chunk(acc, a_thr + 1 * 272, b_thr);
    __syncthreads();
    cpasyncB(smb, (const uint4*)(g_pack + PK4 + 8192), tid);
    CP_WAIT0();
    __syncthreads();

    // ---- iter5: k tap2 ----
    mma_chunk(acc, a_thr + 2 * 272, b_thr);
    __syncthreads();
    cpasyncB(smb, (const uint4*)(g_pack + PK4 + 16384), tid);
    CP_WAIT0();
    __syncthreads();

    // ---- iter6: k tap3; then prefetch Wo (hidden under attention) ----
    mma_chunk(acc, a_thr + 3 * 272, b_thr);
    epi_k(smc, bk, acc, lane, mg, ng);
    __syncthreads();                       // S_ST reads + KP/QP/VP writes done
    cpasyncB(smb, (const uint4*)(g_pack + PO4), tid);

    // ---- attention: warp = head wid; two 32-row passes ----
    {
        const int h = wid;
        const int r = lane >> 2, c = lane & 3;
#pragma unroll 1
        for (int rh = 0; rh < 2; rh++) {
            const int mh = rh * 32;
            float pa[2][8][4];
#pragma unroll
            for (int mt = 0; mt < 2; mt++)
#pragma unroll
                for (int nt = 0; nt < 8; nt++)
#pragma unroll
                    for (int i = 0; i < 4; i++) pa[mt][nt][i] = 0.f;

            // QK^T
#pragma unroll
            for (int mt = 0; mt < 2; mt++) {
                uint32_t A[4];
                ldsm4(A, smb + S_QP_B
                         + (uint32_t)((mh + mt * 16 + (lane & 15)) * 272
                                      + h * 32 + (lane >> 4) * 16));
#pragma unroll
                for (int ntp = 0; ntp < 4; ntp++) {
                    uint4 Bf = lds128(smb + S_KP_B
                                      + (uint32_t)(((h * 4 + ntp) * 32 + lane) * 16));
                    mma16(pa[mt][2 * ntp], A, Bf.x, Bf.y);
                    mma16(pa[mt][2 * ntp + 1], A, Bf.z, Bf.w);
                }
            }

            // masked softmax
            float inv[2][2];
#pragma unroll
            for (int mt = 0; mt < 2; mt++) {
                ull mA = *(const ull*)(smc + S_MSK_B + (mh + mt * 16 + r) * 8);
                ull mB = *(const ull*)(smc + S_MSK_B + (mh + mt * 16 + r + 8) * 8);
                float mxA = -3.0e38f, mxB = -3.0e38f;
#pragma unroll
                for (int nt = 0; nt < 8; nt++) {
                    int c0 = nt * 8 + 2 * c, c1 = c0 + 1;
                    float v;
                    v = ((mA >> c0) & 1) ? pa[mt][nt][0] : -1.0e9f; pa[mt][nt][0] = v; mxA = fmaxf(mxA, v);
                    v = ((mA >> c1) & 1) ? pa[mt][nt][1] : -1.0e9f; pa[mt][nt][1] = v; mxA = fmaxf(mxA, v);
                    v = ((mB >> c0) & 1) ? pa[mt][nt][2] : -1.0e9f; pa[mt][nt][2] = v; mxB = fmaxf(mxB, v);
                    v = ((mB >> c1) & 1) ? pa[mt][nt][3] : -1.0e9f; pa[mt][nt][3] = v; mxB = fmaxf(mxB, v);
                }
                mxA = fmaxf(mxA, __shfl_xor_sync(0xffffffffu, mxA, 1));
                mxA = fmaxf(mxA, __shfl_xor_sync(0xffffffffu, mxA, 2));
                mxB = fmaxf(mxB, __shfl_xor_sync(0xffffffffu, mxB, 1));
                mxB = fmaxf(mxB, __shfl_xor_sync(0xffffffffu, mxB, 2));
                float sA = 0.f, sB = 0.f;
#pragma unroll
                for (int nt = 0; nt < 8; nt++) {
                    float e;
                    e = __expf(pa[mt][nt][0] - mxA); pa[mt][nt][0] = e; sA += e;
                    e = __expf(pa[mt][nt][1] - mxA); pa[mt][nt][1] = e; sA += e;
                    e = __expf(pa[mt][nt][2] - mxB); pa[mt][nt][2] = e; sB += e;
                    e = __expf(pa[mt][nt][3] - mxB); pa[mt][nt][3] = e; sB += e;
                }
                sA += __shfl_xor_sync(0xffffffffu, sA, 1);
                sA += __shfl_xor_sync(0xffffffffu, sA, 2);
                sB += __shfl_xor_sync(0xffffffffu, sB, 1);
                sB += __shfl_xor_sync(0xffffffffu, sB, 2);
                inv[mt][0] = 1.0f / sA;
                inv[mt][1] = 1.0f / sB;
            }

            // P @ V
            float xacc[2][2][4];
#pragma unroll
            for (int mt = 0; mt < 2; mt++)
#pragma unroll
                for (int n2 = 0; n2 < 2; n2++)
#pragma unroll
                    for (int i = 0; i < 4; i++) xacc[mt][n2][i] = 0.f;
#pragma unroll
            for (int mt = 0; mt < 2; mt++) {
#pragma unroll
                for (int kp = 0; kp < 4; kp++) {
                    uint32_t A[4];
                    A[0] = h2(pa[mt][2 * kp][0], pa[mt][2 * kp][1]);
                    A[1] = h2(pa[mt][2 * kp][2], pa[mt][2 * kp][3]);
                    A[2] = h2(pa[mt][2 * kp + 1][0], pa[mt][2 * kp + 1][1]);
                    A[3] = h2(pa[mt][2 * kp + 1][2], pa[mt][2 * kp + 1][3]);
                    uint4 V = lds128(smb + S_VP_B
                                     + (uint32_t)(((h * 4 + kp) * 32 + lane) * 16));
                    mma16(xacc[mt][0], A, V.x, V.y);
                    mma16(xacc[mt][1], A, V.z, V.w);
                }
            }

            // x (normalized, fp16) -> S_IN rows t+2
#pragma unroll
            for (int mt = 0; mt < 2; mt++) {
                int rA = mh + mt * 16 + r, rB = rA + 8;
                float iA = inv[mt][0], iB = inv[mt][1];
#pragma unroll
                for (int n2 = 0; n2 < 2; n2++) {
                    int col = h * 16 + n2 * 8 + 2 * c;
                    *(uint32_t*)(smc + S_IN_B + (2 + rA) * 272 + col * 2) =
                        h2(xacc[mt][n2][0] * iA, xacc[mt][n2][1] * iA);
                    *(uint32_t*)(smc + S_IN_B + (2 + rB) * 272 + col * 2) =
                        h2(xacc[mt][n2][2] * iB, xacc[mt][n2][3] * iB);
                }
            }
        }
    }
    CP_WAIT0();
    __syncthreads();                       // x rows + Wo chunk visible

    // ---- iter7: output projection ----
    zacc(acc);
    mma_chunk(acc, a_thr + 2 * 272, b_thr);
    epi_g(out + base, bo, acc, lane, mg, ng);
}

extern "C" void kernel_launch(void* const* d_in, const int* in_sizes, int n_in,
                              void* d_out, int out_size) {
    (void)in_sizes; (void)n_in; (void)out_size;
    const float* query = (const float*)d_in[0];
    const float* key   = (const float*)d_in[1];
    const float* value = (const float*)d_in[2];
    const int*   mask  = (const int*)d_in[3];
    const float* Wq = (const float*)d_in[4];
    const float* bq = (const float*)d_in[5];
    const float* Wk = (const float*)d_in[6];
    const float* bk = (const float*)d_in[7];
    const float* Wv = (const float*)d_in[8];
    const float* bv = (const float*)d_in[9];
    const float* Wo = (const float*)d_in[10];
    const float* bo = (const float*)d_in[11];
    float* out = (float*)d_out;

    cudaFuncSetAttribute(attn_kernel, cudaFuncAttributeMaxDynamicSharedMemorySize, SMEM_BYTES);
    prep_kernel<<<64, 256>>>(Wq, Wk, Wv, Wo);
    attn_kernel<<<4096, 256, SMEM_BYTES>>>(query, key, value, mask, bq, bk, bv, bo, out);
}

// round 13
// speedup vs baseline: 1.1943x; 1.0536x over previous
#include <cuda_runtime.h>
#include <cuda_fp16.h>
#include <cstdint>

// B=8, N=512, T=64, D=128, H=8, DK=16, K=3.
// R13: ONE (b,n) tile per CTA (M=64), 256 thr = 8 warps, warp tile 32x32, 2 CTA/SM.
// fp16 MMA, fp32 accumulate. K and V stored as plain row-major fp16 tiles;
// attention B-fragments built with ldmatrix (K: non-trans, V: trans).

// byte offsets in dynamic smem (per CTA 104000 B)
#define S_IN_B   0          // 68 rows x 272B fp16 (rows 0,1,66,67 zero pad)
#define S_ST_B   18496      // 32KB packed-B weight chunk
#define S_QP_B   51264      // 64 x 272B fp16 q tile
#define S_KT_B   68672      // 64 x 272B fp16 k tile (row-major, all heads)
#define S_VT_B   86080      // 64 x 272B fp16 v tile
#define S_MSK_B  103488     // 64 x ull row masks
#define SMEM_BYTES 104000

// g_pack chunk offsets (uint32 units; each chunk = 8192 uint32 = 32KB)
#define PQ4 0
#define PK4 24576
#define PV4 49152
#define PO4 57344

typedef unsigned long long ull;
__device__ uint32_t g_pack[65536];

// ---------------- PTX helpers ----------------
__device__ __forceinline__ uint32_t smem_u32(const void* p) {
    uint32_t a;
    asm("{ .reg .u64 t; cvta.to.shared.u64 t, %1; cvt.u32.u64 %0, t; }" : "=r"(a) : "l"(p));
    return a;
}
__device__ __forceinline__ uint32_t h2(float lo, float hi) {
    uint32_t r; asm("cvt.rn.f16x2.f32 %0, %1, %2;" : "=r"(r) : "f"(hi), "f"(lo)); return r;
}
__device__ __forceinline__ uint4 lds128(uint32_t a) {
    uint4 v;
    asm volatile("ld.shared.v4.b32 {%0,%1,%2,%3}, [%4];"
                 : "=r"(v.x), "=r"(v.y), "=r"(v.z), "=r"(v.w) : "r"(a));
    return v;
}
__device__ __forceinline__ void ldsm4(uint32_t (&r)[4], uint32_t a) {
    asm volatile("ldmatrix.sync.aligned.m8n8.x4.shared.b16 {%0,%1,%2,%3}, [%4];"
                 : "=r"(r[0]), "=r"(r[1]), "=r"(r[2]), "=r"(r[3]) : "r"(a));
}
__device__ __forceinline__ void ldsm4t(uint32_t (&r)[4], uint32_t a) {
    asm volatile("ldmatrix.sync.aligned.m8n8.x4.trans.shared.b16 {%0,%1,%2,%3}, [%4];"
                 : "=r"(r[0]), "=r"(r[1]), "=r"(r[2]), "=r"(r[3]) : "r"(a));
}
__device__ __forceinline__ void mma16(float (&c)[4], const uint32_t (&a)[4],
                                      uint32_t b0, uint32_t b1) {
    asm volatile(
        "mma.sync.aligned.m16n8k16.row.col.f32.f16.f16.f32 "
        "{%0,%1,%2,%3},{%4,%5,%6,%7},{%8,%9},{%0,%1,%2,%3};"
        : "+f"(c[0]), "+f"(c[1]), "+f"(c[2]), "+f"(c[3])
        : "r"(a[0]), "r"(a[1]), "r"(a[2]), "r"(a[3]), "r"(b0), "r"(b1));
}
// register-free global->shared prefetch of one 32KB weight chunk (256 thr: 8 ops)
__device__ __forceinline__ void cpasyncB(uint32_t smb, const uint4* __restrict__ g4, int tid) {
#pragma unroll
    for (int r = 0; r < 8; r++) {
        uint32_t dst = smb + S_ST_B + (uint32_t)((tid + r * 256) * 16);
        asm volatile("cp.async.cg.shared.global [%0], [%1], 16;"
                     :: "r"(dst), "l"(g4 + tid + r * 256) : "memory");
    }
    asm volatile("cp.async.commit_group;" ::: "memory");
}
#define CP_WAIT0() asm volatile("cp.async.wait_group 0;" ::: "memory")

// ---------------- prep: pack weights as fp16 B-fragments ----------------
__global__ void prep_kernel(const float* __restrict__ Wq, const float* __restrict__ Wk,
                            const float* __restrict__ Wv, const float* __restrict__ Wo) {
    int idx = blockIdx.x * blockDim.x + threadIdx.x;   // 16384
    if (idx >= 16384) return;
    const float* W; int base4, within, j = 0, conv; float sc = 1.0f;
    if (idx < 6144)       { W = Wq; j = idx >> 11; within = idx & 2047; base4 = PQ4 / 4 + idx; conv = 1; sc = 0.25f; }
    else if (idx < 12288) { int i2 = idx - 6144; W = Wk; j = i2 >> 11; within = i2 & 2047; base4 = PK4 / 4 + i2; conv = 1; }
    else if (idx < 14336) { int i2 = idx - 12288; W = Wv; within = i2; base4 = PV4 / 4 + i2; conv = 0; }
    else                  { int i2 = idx - 14336; W = Wo; within = i2; base4 = PO4 / 4 + i2; conv = 0; }
    int lane = within & 31, njp = (within >> 5) & 7, ksp = within >> 8;
    int n0 = njp * 16 + (lane >> 2);
    int n1 = n0 + 8;
    int k0 = ksp * 16 + 2 * (lane & 3);
    float w[8];
    if (conv) {
        w[0] = W[(n0 * 128 + k0) * 3 + j];     w[1] = W[(n0 * 128 + k0 + 1) * 3 + j];
        w[2] = W[(n0 * 128 + k0 + 8) * 3 + j]; w[3] = W[(n0 * 128 + k0 + 9) * 3 + j];
        w[4] = W[(n1 * 128 + k0) * 3 + j];     w[5] = W[(n1 * 128 + k0 + 1) * 3 + j];
        w[6] = W[(n1 * 128 + k0 + 8) * 3 + j]; w[7] = W[(n1 * 128 + k0 + 9) * 3 + j];
    } else {
        w[0] = W[n0 * 128 + k0];     w[1] = W[n0 * 128 + k0 + 1];
        w[2] = W[n0 * 128 + k0 + 8]; w[3] = W[n0 * 128 + k0 + 9];
        w[4] = W[n1 * 128 + k0];     w[5] = W[n1 * 128 + k0 + 1];
        w[6] = W[n1 * 128 + k0 + 8]; w[7] = W[n1 * 128 + k0 + 9];
    }
    uint4 o;
    o.x = h2(w[0] * sc, w[1] * sc);
    o.y = h2(w[2] * sc, w[3] * sc);
    o.z = h2(w[4] * sc, w[5] * sc);
    o.w = h2(w[6] * sc, w[7] * sc);
    ((uint4*)g_pack)[base4] = o;
}

// ---------------- building blocks ----------------
__device__ __forceinline__ void load_input(char* smc, const float* __restrict__ g, int tid) {
#pragma unroll
    for (int r = 0; r < 8; r++) {
        int idx = tid + r * 256;                       // 2048 float4 (1 tile)
        float4 f = *(const float4*)(g + idx * 4);
        int t = idx >> 5, d = (idx & 31) * 4;
        uint2 v;
        v.x = h2(f.x, f.y);
        v.y = h2(f.z, f.w);
        *(uint2*)(smc + S_IN_B + (t + 2) * 272 + d * 2) = v;
    }
}
// one K=128 chunk, warp tile 32x32
__device__ __forceinline__ void mma_chunk(float (&acc)[2][4][4], uint32_t a0, uint32_t b0) {
#pragma unroll
    for (int ksp = 0; ksp < 8; ksp++) {
        uint32_t A0[4], A1[4];
        ldsm4(A0, a0 + ksp * 32);
        ldsm4(A1, a0 + 16 * 272 + ksp * 32);
        uint4 B01 = lds128(b0 + ksp * 4096);
        uint4 B23 = lds128(b0 + ksp * 4096 + 512);
        mma16(acc[0][0], A0, B01.x, B01.y);
        mma16(acc[0][1], A0, B01.z, B01.w);
        mma16(acc[0][2], A0, B23.x, B23.y);
        mma16(acc[0][3], A0, B23.z, B23.w);
        mma16(acc[1][0], A1, B01.x, B01.y);
        mma16(acc[1][1], A1, B01.z, B01.w);
        mma16(acc[1][2], A1, B23.x, B23.y);
        mma16(acc[1][3], A1, B23.z, B23.w);
    }
}
__device__ __forceinline__ void zacc(float (&acc)[2][4][4]) {
#pragma unroll
    for (int s = 0; s < 2; s++)
#pragma unroll
        for (int i = 0; i < 4; i++)
#pragma unroll
            for (int k = 0; k < 4; k++) acc[s][i][k] = 0.f;
}
// generic fp16 row-major tile epilogue (u32 stores, conflict-free)
__device__ __forceinline__ void epi_s(char* smc, int baseoff, const float* __restrict__ bias,
                                      float bscale, float (&acc)[2][4][4],
                                      int lane, int mg, int ng) {
#pragma unroll
    for (int msub = 0; msub < 2; msub++) {
        int r0 = mg * 32 + msub * 16 + (lane >> 2);
#pragma unroll
        for (int nt = 0; nt < 4; nt++) {
            int col = ng * 32 + nt * 8 + (lane & 3) * 2;
            float2 bb = *(const float2*)(bias + col);
            *(uint32_t*)(smc + baseoff + r0 * 272 + col * 2) =
                h2(acc[msub][nt][0] + bb.x * bscale, acc[msub][nt][1] + bb.y * bscale);
            *(uint32_t*)(smc + baseoff + (r0 + 8) * 272 + col * 2) =
                h2(acc[msub][nt][2] + bb.x * bscale, acc[msub][nt][3] + bb.y * bscale);
        }
    }
}
__device__ __forceinline__ void epi_g(float* __restrict__ dst, const float* __restrict__ bias,
                                      float (&acc)[2][4][4], int lane, int mg, int ng) {
#pragma unroll
    for (int msub = 0; msub < 2; msub++) {
        int r0 = mg * 32 + msub * 16 + (lane >> 2);
#pragma unroll
        for (int nt = 0; nt < 4; nt++) {
            int col = ng * 32 + nt * 8 + (lane & 3) * 2;
            float2 bb = *(const float2*)(bias + col);
            *(float2*)(dst + r0 * 128 + col) = make_float2(acc[msub][nt][0] + bb.x, acc[msub][nt][1] + bb.y);
            *(float2*)(dst + (r0 + 8) * 128 + col) = make_float2(acc[msub][nt][2] + bb.x, acc[msub][nt][3] + bb.y);
        }
    }
}

__global__ void __launch_bounds__(256, 2)
attn_kernel(const float* __restrict__ query, const float* __restrict__ key,
            const float* __restrict__ value, const int* __restrict__ mask,
            const float* __restrict__ bq, const float* __restrict__ bk,
            const float* __restrict__ bv, const float* __restrict__ bo,
            float* __restrict__ out)
{
    extern __shared__ char smc[];
    uint32_t smb = smem_u32(smc);
    const int tid = threadIdx.x, lane = tid & 31, wid = tid >> 5;
    const int cta = blockIdx.x, b = cta >> 9;
    const long long base = (long long)cta * 8192;

    const int mg = wid >> 2, ng = wid & 3;
    const int rowbase = mg * 32 + (lane & 15);
    const uint32_t a_thr = smb + S_IN_B + (uint32_t)(rowbase * 272 + (lane >> 4) * 16);
    const uint32_t b_thr = smb + S_ST_B + (uint32_t)((ng * 64 + lane) * 16);

    // ---- prologue ----
    cpasyncB(smb, (const uint4*)(g_pack + PV4), tid);
    // zero pad rows 0,1,66,67: 4 rows x 272B = 136 u64
    if (tid < 136) {
        int rr = tid / 34, off = tid - rr * 34;
        int row = (rr < 2) ? rr : (64 + rr);
        *(ull*)(smc + S_IN_B + row * 272 + off * 8) = 0ull;
    }
    if (tid < 64) {
        ull m = 0;
        const int4* mr = (const int4*)(mask + b * 4096 + tid * 64);
#pragma unroll
        for (int u = 0; u < 16; u++) {
            int4 mm = mr[u];
            ull bits = (ull)(mm.x != 0) | ((ull)(mm.y != 0) << 1) |
                       ((ull)(mm.z != 0) << 2) | ((ull)(mm.w != 0) << 3);
            m |= bits << (u * 4);
        }
        *(ull*)(smc + S_MSK_B + tid * 8) = m;
    }
    load_input(smc, value + base, tid);
    CP_WAIT0();
    __syncthreads();

    float acc[2][4][4];

    // ---- iter0: v GEMM -> VT (row-major) ----
    zacc(acc);
    mma_chunk(acc, a_thr + 2 * 272, b_thr);
    epi_s(smc, S_VT_B, bv, 1.0f, acc, lane, mg, ng);
    __syncthreads();
    cpasyncB(smb, (const uint4*)(g_pack + PQ4), tid);
    load_input(smc, query + base, tid);
    CP_WAIT0();
    __syncthreads();

    // ---- iter1-3: q conv taps 0,1,2 -> QP ----
    zacc(acc);
    mma_chunk(acc, a_thr + 0 * 272, b_thr);
    __syncthreads();
    cpasyncB(smb, (const uint4*)(g_pack + PQ4 + 8192), tid);
    CP_WAIT0();
    __syncthreads();
    mma_chunk(acc, a_thr + 1 * 272, b_thr);
    __syncthreads();
    cpasyncB(smb, (const uint4*)(g_pack + PQ4 + 16384), tid);
    CP_WAIT0();
    __syncthreads();
    mma_chunk(acc, a_thr + 2 * 272, b_thr);
    epi_s(smc, S_QP_B, bq, 0.25f, acc, lane, mg, ng);
    __syncthreads();
    cpasyncB(smb, (const uint4*)(g_pack + PK4), tid);
    load_input(smc, key + base, tid);
    CP_WAIT0();
    __syncthreads();

    // ---- iter4-6: k conv taps 1,2,3 -> KT (row-major) ----
    zacc(acc);
    mma_chunk(acc, a_thr + 1 * 272, b_thr);
    __syncthreads();
    cpasyncB(smb, (const uint4*)(g_pack + PK4 + 8192), tid);
    CP_WAIT0();
    __syncthreads();
    mma_chunk(acc, a_thr + 2 * 272, b_thr);
    __syncthreads();
    cpasyncB(smb, (const uint4*)(g_pack + PK4 + 16384), tid);
    CP_WAIT0();
    __syncthreads();
    mma_chunk(acc, a_thr + 3 * 272, b_thr);
    epi_s(smc, S_KT_B, bk, 1.0f, acc, lane, mg, ng);
    __syncthreads();                       // S_ST reads + KT/QP/VT writes done
    cpasyncB(smb, (const uint4*)(g_pack + PO4), tid);   // Wo hides under attention

    // ---- attention: warp = head wid; two 32-row passes ----
    {
        const int h = wid;
        const int r = lane >> 2, c = lane & 3;
        // K B-frag address: rows = s (non-trans), 2 n8-blocks x 2 k-halves
        const uint32_t kt_thr = smb + S_KT_B
            + (uint32_t)((((lane >> 4) << 3) + (lane & 7)) * 272
                         + h * 32 + ((lane >> 3) & 1) * 16);
        // V B-frag address: rows = s (trans), b0/b1 = s-halves, 2 n8-blocks
        const uint32_t vt_thr = smb + S_VT_B
            + (uint32_t)(((((lane >> 3) & 1) << 3) + (lane & 7)) * 272
                         + h * 32 + (lane >> 4) * 16);
#pragma unroll 1
        for (int rh = 0; rh < 2; rh++) {
            const int mh = rh * 32;
            float pa[2][8][4];
#pragma unroll
            for (int mt = 0; mt < 2; mt++)
#pragma unroll
                for (int nt = 0; nt < 8; nt++)
#pragma unroll
                    for (int i = 0; i < 4; i++) pa[mt][nt][i] = 0.f;

            // QK^T: B-frags from row-major KT via plain ldmatrix
#pragma unroll
            for (int mt = 0; mt < 2; mt++) {
                uint32_t A[4];
                ldsm4(A, smb + S_QP_B
                         + (uint32_t)((mh + mt * 16 + (lane & 15)) * 272
                                      + h * 32 + (lane >> 4) * 16));
#pragma unroll
                for (int ntp = 0; ntp < 4; ntp++) {
                    uint32_t Bf[4];
                    ldsm4(Bf, kt_thr + (uint32_t)(ntp * 16 * 272));
                    mma16(pa[mt][2 * ntp], A, Bf[0], Bf[1]);
                    mma16(pa[mt][2 * ntp + 1], A, Bf[2], Bf[3]);
                }
            }

            // masked softmax
            float inv[2][2];
#pragma unroll
            for (int mt = 0; mt < 2; mt++) {
                ull mA = *(const ull*)(smc + S_MSK_B + (mh + mt * 16 + r) * 8);
                ull mB = *(const ull*)(smc + S_MSK_B + (mh + mt * 16 + r + 8) * 8);
                float mxA = -3.0e38f, mxB = -3.0e38f;
#pragma unroll
                for (int nt = 0; nt < 8; nt++) {
                    int c0 = nt * 8 + 2 * c, c1 = c0 + 1;
                    float v;
                    v = ((mA >> c0) & 1) ? pa[mt][nt][0] : -1.0e9f; pa[mt][nt][0] = v; mxA = fmaxf(mxA, v);
                    v = ((mA >> c1) & 1) ? pa[mt][nt][1] : -1.0e9f; pa[mt][nt][1] = v; mxA = fmaxf(mxA, v);
                    v = ((mB >> c0) & 1) ? pa[mt][nt][2] : -1.0e9f; pa[mt][nt][2] = v; mxB = fmaxf(mxB, v);
                    v = ((mB >> c1) & 1) ? pa[mt][nt][3] : -1.0e9f; pa[mt][nt][3] = v; mxB = fmaxf(mxB, v);
                }
                mxA = fmaxf(mxA, __shfl_xor_sync(0xffffffffu, mxA, 1));
                mxA = fmaxf(mxA, __shfl_xor_sync(0xffffffffu, mxA, 2));
                mxB = fmaxf(mxB, __shfl_xor_sync(0xffffffffu, mxB, 1));
                mxB = fmaxf(mxB, __shfl_xor_sync(0xffffffffu, mxB, 2));
                float sA = 0.f, sB = 0.f;
#pragma unroll
                for (int nt = 0; nt < 8; nt++) {
                    float e;
                    e = __expf(pa[mt][nt][0] - mxA); pa[mt][nt][0] = e; sA += e;
                    e = __expf(pa[mt][nt][1] - mxA); pa[mt][nt][1] = e; sA += e;
                    e = __expf(pa[mt][nt][2] - mxB); pa[mt][nt][2] = e; sB += e;
                    e = __expf(pa[mt][nt][3] - mxB); pa[mt][nt][3] = e; sB += e;
                }
                sA += __shfl_xor_sync(0xffffffffu, sA, 1);
                sA += __shfl_xor_sync(0xffffffffu, sA, 2);
                sB += __shfl_xor_sync(0xffffffffu, sB, 1);
                sB += __shfl_xor_sync(0xffffffffu, sB, 2);
                inv[mt][0] = 1.0f / sA;
                inv[mt][1] = 1.0f / sB;
            }

            // P @ V: V B-frags from row-major VT via ldmatrix.trans (hoisted over mt)
            float xacc[2][2][4];
#pragma unroll
            for (int mt = 0; mt < 2; mt++)
#pragma unroll
                for (int n2 = 0; n2 < 2; n2++)
#pragma unroll
                    for (int i = 0; i < 4; i++) xacc[mt][n2][i] = 0.f;
#pragma unroll
            for (int kp = 0; kp < 4; kp++) {
                uint32_t Vf[4];
                ldsm4t(Vf, vt_thr + (uint32_t)(kp * 16 * 272));
#pragma unroll
                for (int mt = 0; mt < 2; mt++) {
                    uint32_t A[4];
                    A[0] = h2(pa[mt][2 * kp][0], pa[mt][2 * kp][1]);
                    A[1] = h2(pa[mt][2 * kp][2], pa[mt][2 * kp][3]);
                    A[2] = h2(pa[mt][2 * kp + 1][0], pa[mt][2 * kp + 1][1]);
                    A[3] = h2(pa[mt][2 * kp + 1][2], pa[mt][2 * kp + 1][3]);
                    mma16(xacc[mt][0], A, Vf[0], Vf[1]);
                    mma16(xacc[mt][1], A, Vf[2], Vf[3]);
                }
            }

            // x (normalized, fp16) -> S_IN rows t+2
#pragma unroll
            for (int mt = 0; mt < 2; mt++) {
                int rA = mh + mt * 16 + r, rB = rA + 8;
                float iA = inv[mt][0], iB = inv[mt][1];
#pragma unroll
                for (int n2 = 0; n2 < 2; n2++) {
                    int col = h * 16 + n2 * 8 + 2 * c;
                    *(uint32_t*)(smc + S_IN_B + (2 + rA) * 272 + col * 2) =
                        h2(xacc[mt][n2][0] * iA, xacc[mt][n2][1] * iA);
                    *(uint32_t*)(smc + S_IN_B + (2 + rB) * 272 + col * 2) =
                        h2(xacc[mt][n2][2] * iB, xacc[mt][n2][3] * iB);
                }
            }
        }
    }
    CP_WAIT0();
    __syncthreads();                       // x rows + Wo chunk visible

    // ---- iter7: output projection ----
    zacc(acc);
    mma_chunk(acc, a_thr + 2 * 272, b_thr);
    epi_g(out + base, bo, acc, lane, mg, ng);
}

extern "C" void kernel_launch(void* const* d_in, const int* in_sizes, int n_in,
                              void* d_out, int out_size) {
    (void)in_sizes; (void)n_in; (void)out_size;
    const float* query = (const float*)d_in[0];
    const float* key   = (const float*)d_in[1];
    const float* value = (const float*)d_in[2];
    const int*   mask  = (const int*)d_in[3];
    const float* Wq = (const float*)d_in[4];
    const float* bq = (const float*)d_in[5];
    const float* Wk = (const float*)d_in[6];
    const float* bk = (const float*)d_in[7];
    const float* Wv = (const float*)d_in[8];
    const float* bv = (const float*)d_in[9];
    const float* Wo = (const float*)d_in[10];
    const float* bo = (const float*)d_in[11];
    float* out = (float*)d_out;

    cudaFuncSetAttribute(attn_kernel, cudaFuncAttributeMaxDynamicSharedMemorySize, SMEM_BYTES);
    prep_kernel<<<64, 256>>>(Wq, Wk, Wv, Wo);
    attn_kernel<<<4096, 256, SMEM_BYTES>>>(query, key, value, mask, bq, bk, bv, bo, out);
}

// round 14
// speedup vs baseline: 1.2915x; 1.0813x over previous
#include <cuda_runtime.h>
#include <cuda_fp16.h>
#include <cstdint>

// B=8, N=512, T=64, D=128, H=8, DK=16, K=3.
// R14: ONE (b,n) tile per CTA (M=64), 256 thr = 8 warps, warp tile 32x32, 2 CTA/SM.
// fp16 MMA, fp32 accumulate. 16KB half-chunk cp.async double-buffer pipeline.

// byte offsets in dynamic smem (per CTA 104000 B)
#define S_IN_B   0          // 68 rows x 272B fp16 (rows 0,1,66,67 zero pad)
#define S_ST_B   18496      // 2 x 16KB double-buffered weight half-chunk
#define S_QP_B   51264      // 64 x 272B fp16 q tile
#define S_KT_B   68672      // 64 x 272B fp16 k tile (row-major)
#define S_VT_B   86080      // 64 x 272B fp16 v tile
#define S_MSK_B  103488     // 64 x ull row masks
#define SMEM_BYTES 104000

// g_pack offsets (uint32 units). 32KB chunk = 8192 u32; half = 4096 u32.
#define PQ4 0
#define PK4 24576
#define PV4 49152
#define PO4 57344

typedef unsigned long long ull;
__device__ uint32_t g_pack[65536];

// ---------------- PTX helpers ----------------
__device__ __forceinline__ uint32_t smem_u32(const void* p) {
    uint32_t a;
    asm("{ .reg .u64 t; cvta.to.shared.u64 t, %1; cvt.u32.u64 %0, t; }" : "=r"(a) : "l"(p));
    return a;
}
__device__ __forceinline__ uint32_t h2(float lo, float hi) {
    uint32_t r; asm("cvt.rn.f16x2.f32 %0, %1, %2;" : "=r"(r) : "f"(hi), "f"(lo)); return r;
}
__device__ __forceinline__ uint4 lds128(uint32_t a) {
    uint4 v;
    asm volatile("ld.shared.v4.b32 {%0,%1,%2,%3}, [%4];"
                 : "=r"(v.x), "=r"(v.y), "=r"(v.z), "=r"(v.w) : "r"(a));
    return v;
}
__device__ __forceinline__ void ldsm4(uint32_t (&r)[4], uint32_t a) {
    asm volatile("ldmatrix.sync.aligned.m8n8.x4.shared.b16 {%0,%1,%2,%3}, [%4];"
                 : "=r"(r[0]), "=r"(r[1]), "=r"(r[2]), "=r"(r[3]) : "r"(a));
}
__device__ __forceinline__ void ldsm4t(uint32_t (&r)[4], uint32_t a) {
    asm volatile("ldmatrix.sync.aligned.m8n8.x4.trans.shared.b16 {%0,%1,%2,%3}, [%4];"
                 : "=r"(r[0]), "=r"(r[1]), "=r"(r[2]), "=r"(r[3]) : "r"(a));
}
__device__ __forceinline__ void mma16(float (&c)[4], const uint32_t (&a)[4],
                                      uint32_t b0, uint32_t b1) {
    asm volatile(
        "mma.sync.aligned.m16n8k16.row.col.f32.f16.f16.f32 "
        "{%0,%1,%2,%3},{%4,%5,%6,%7},{%8,%9},{%0,%1,%2,%3};"
        : "+f"(c[0]), "+f"(c[1]), "+f"(c[2]), "+f"(c[3])
        : "r"(a[0]), "r"(a[1]), "r"(a[2]), "r"(a[3]), "r"(b0), "r"(b1));
}
// register-free global->shared prefetch of one 16KB half-chunk (256 thr: 4 ops)
__device__ __forceinline__ void cpasyncH(uint32_t smb, int buf, const uint32_t* __restrict__ g,
                                         int tid) {
    const uint4* g4 = (const uint4*)g;
#pragma unroll
    for (int r = 0; r < 4; r++) {
        uint32_t dst = smb + S_ST_B + (uint32_t)(buf * 16384 + (tid + r * 256) * 16);
        asm volatile("cp.async.cg.shared.global [%0], [%1], 16;"
                     :: "r"(dst), "l"(g4 + tid + r * 256) : "memory");
    }
    asm volatile("cp.async.commit_group;" ::: "memory");
}
#define CP_WAIT0() asm volatile("cp.async.wait_group 0;" ::: "memory")

// ---------------- prep: pack weights as fp16 B-fragments (unchanged) ------------
__global__ void prep_kernel(const float* __restrict__ Wq, const float* __restrict__ Wk,
                            const float* __restrict__ Wv, const float* __restrict__ Wo) {
    int idx = blockIdx.x * blockDim.x + threadIdx.x;   // 16384
    if (idx >= 16384) return;
    const float* W; int base4, within, j = 0, conv; float sc = 1.0f;
    if (idx < 6144)       { W = Wq; j = idx >> 11; within = idx & 2047; base4 = PQ4 / 4 + idx; conv = 1; sc = 0.25f; }
    else if (idx < 12288) { int i2 = idx - 6144; W = Wk; j = i2 >> 11; within = i2 & 2047; base4 = PK4 / 4 + i2; conv = 1; }
    else if (idx < 14336) { int i2 = idx - 12288; W = Wv; within = i2; base4 = PV4 / 4 + i2; conv = 0; }
    else                  { int i2 = idx - 14336; W = Wo; within = i2; base4 = PO4 / 4 + i2; conv = 0; }
    int lane = within & 31, njp = (within >> 5) & 7, ksp = within >> 8;
    int n0 = njp * 16 + (lane >> 2);
    int n1 = n0 + 8;
    int k0 = ksp * 16 + 2 * (lane & 3);
    float w[8];
    if (conv) {
        w[0] = W[(n0 * 128 + k0) * 3 + j];     w[1] = W[(n0 * 128 + k0 + 1) * 3 + j];
        w[2] = W[(n0 * 128 + k0 + 8) * 3 + j]; w[3] = W[(n0 * 128 + k0 + 9) * 3 + j];
        w[4] = W[(n1 * 128 + k0) * 3 + j];     w[5] = W[(n1 * 128 + k0 + 1) * 3 + j];
        w[6] = W[(n1 * 128 + k0 + 8) * 3 + j]; w[7] = W[(n1 * 128 + k0 + 9) * 3 + j];
    } else {
        w[0] = W[n0 * 128 + k0];     w[1] = W[n0 * 128 + k0 + 1];
        w[2] = W[n0 * 128 + k0 + 8]; w[3] = W[n0 * 128 + k0 + 9];
        w[4] = W[n1 * 128 + k0];     w[5] = W[n1 * 128 + k0 + 1];
        w[6] = W[n1 * 128 + k0 + 8]; w[7] = W[n1 * 128 + k0 + 9];
    }
    uint4 o;
    o.x = h2(w[0] * sc, w[1] * sc);
    o.y = h2(w[2] * sc, w[3] * sc);
    o.z = h2(w[4] * sc, w[5] * sc);
    o.w = h2(w[6] * sc, w[7] * sc);
    ((uint4*)g_pack)[base4] = o;
}

// ---------------- building blocks ----------------
__device__ __forceinline__ void load_input(char* smc, const float* __restrict__ g, int tid) {
#pragma unroll
    for (int r = 0; r < 8; r++) {
        int idx = tid + r * 256;
        float4 f = *(const float4*)(g + idx * 4);
        int t = idx >> 5, d = (idx & 31) * 4;
        uint2 v;
        v.x = h2(f.x, f.y);
        v.y = h2(f.z, f.w);
        *(uint2*)(smc + S_IN_B + (t + 2) * 272 + d * 2) = v;
    }
}
// one 16KB half-chunk: 4 k16-steps, warp tile 32x32
__device__ __forceinline__ void mma_half(float (&acc)[2][4][4], uint32_t a0, uint32_t b0) {
#pragma unroll
    for (int ksp = 0; ksp < 4; ksp++) {
        uint32_t A0[4], A1[4];
        ldsm4(A0, a0 + ksp * 32);
        ldsm4(A1, a0 + 16 * 272 + ksp * 32);
        uint4 B01 = lds128(b0 + ksp * 4096);
        uint4 B23 = lds128(b0 + ksp * 4096 + 512);
        mma16(acc[0][0], A0, B01.x, B01.y);
        mma16(acc[0][1], A0, B01.z, B01.w);
        mma16(acc[0][2], A0, B23.x, B23.y);
        mma16(acc[0][3], A0, B23.z, B23.w);
        mma16(acc[1][0], A1, B01.x, B01.y);
        mma16(acc[1][1], A1, B01.z, B01.w);
        mma16(acc[1][2], A1, B23.x, B23.y);
        mma16(acc[1][3], A1, B23.z, B23.w);
    }
}
__device__ __forceinline__ void zacc(float (&acc)[2][4][4]) {
#pragma unroll
    for (int s = 0; s < 2; s++)
#pragma unroll
        for (int i = 0; i < 4; i++)
#pragma unroll
            for (int k = 0; k < 4; k++) acc[s][i][k] = 0.f;
}
__device__ __forceinline__ void epi_s(char* smc, int baseoff, const float* __restrict__ bias,
                                      float bscale, float (&acc)[2][4][4],
                                      int lane, int mg, int ng) {
#pragma unroll
    for (int msub = 0; msub < 2; msub++) {
        int r0 = mg * 32 + msub * 16 + (lane >> 2);
#pragma unroll
        for (int nt = 0; nt < 4; nt++) {
            int col = ng * 32 + nt * 8 + (lane & 3) * 2;
            float2 bb = *(const float2*)(bias + col);
            *(uint32_t*)(smc + baseoff + r0 * 272 + col * 2) =
                h2(acc[msub][nt][0] + bb.x * bscale, acc[msub][nt][1] + bb.y * bscale);
            *(uint32_t*)(smc + baseoff + (r0 + 8) * 272 + col * 2) =
                h2(acc[msub][nt][2] + bb.x * bscale, acc[msub][nt][3] + bb.y * bscale);
        }
    }
}
__device__ __forceinline__ void epi_g(float* __restrict__ dst, const float* __restrict__ bias,
                                      float (&acc)[2][4][4], int lane, int mg, int ng) {
#pragma unroll
    for (int msub = 0; msub < 2; msub++) {
        int r0 = mg * 32 + msub * 16 + (lane >> 2);
#pragma unroll
        for (int nt = 0; nt < 4; nt++) {
            int col = ng * 32 + nt * 8 + (lane & 3) * 2;
            float2 bb = *(const float2*)(bias + col);
            *(float2*)(dst + r0 * 128 + col) = make_float2(acc[msub][nt][0] + bb.x, acc[msub][nt][1] + bb.y);
            *(float2*)(dst + (r0 + 8) * 128 + col) = make_float2(acc[msub][nt][2] + bb.x, acc[msub][nt][3] + bb.y);
        }
    }
}

__global__ void __launch_bounds__(256, 2)
attn_kernel(const float* __restrict__ query, const float* __restrict__ key,
            const float* __restrict__ value, const int* __restrict__ mask,
            const float* __restrict__ bq, const float* __restrict__ bk,
            const float* __restrict__ bv, const float* __restrict__ bo,
            float* __restrict__ out)
{
    extern __shared__ char smc[];
    uint32_t smb = smem_u32(smc);
    const int tid = threadIdx.x, lane = tid & 31, wid = tid >> 5;
    const int cta = blockIdx.x, b = cta >> 9;
    const long long base = (long long)cta * 8192;

    const int mg = wid >> 2, ng = wid & 3;
    const int rowbase = mg * 32 + (lane & 15);
    const uint32_t a_thr = smb + S_IN_B + (uint32_t)(rowbase * 272 + (lane >> 4) * 16);
    const uint32_t b_lane = (uint32_t)((ng * 64 + lane) * 16);
    const uint32_t bb0 = smb + S_ST_B + b_lane;
    const uint32_t bb1 = smb + S_ST_B + 16384u + b_lane;

    // ---- prologue: c0 = V-half0 ----
    cpasyncH(smb, 0, g_pack + PV4, tid);
    if (tid < 136) {
        int rr = tid / 34, off = tid - rr * 34;
        int row = (rr < 2) ? rr : (64 + rr);
        *(ull*)(smc + S_IN_B + row * 272 + off * 8) = 0ull;
    }
    if (tid < 64) {
        ull m = 0;
        const int4* mr = (const int4*)(mask + b * 4096 + tid * 64);
#pragma unroll
        for (int u = 0; u < 16; u++) {
            int4 mm = mr[u];
            ull bits = (ull)(mm.x != 0) | ((ull)(mm.y != 0) << 1) |
                       ((ull)(mm.z != 0) << 2) | ((ull)(mm.w != 0) << 3);
            m |= bits << (u * 4);
        }
        *(ull*)(smc + S_MSK_B + tid * 8) = m;
    }
    load_input(smc, value + base, tid);
    CP_WAIT0();
    __syncthreads();

    float acc[2][4][4];
    zacc(acc);

    // iter0: V h0 (b0); prefetch V h1 -> b1
    cpasyncH(smb, 1, g_pack + PV4 + 4096, tid);
    mma_half(acc, a_thr + 2 * 272, bb0);
    CP_WAIT0(); __syncthreads();
    // iter1: V h1 (b1); prefetch Q0 h0 -> b0
    cpasyncH(smb, 0, g_pack + PQ4, tid);
    mma_half(acc, a_thr + 2 * 272 + 128, bb1);
    epi_s(smc, S_VT_B, bv, 1.0f, acc, lane, mg, ng);
    CP_WAIT0(); __syncthreads();
    // input switch: value -> query (all V reads of S_IN done)
    load_input(smc, query + base, tid);
    __syncthreads();

    zacc(acc);
    // iter2: Q0 h0 (b0); prefetch Q0 h1 -> b1
    cpasyncH(smb, 1, g_pack + PQ4 + 4096, tid);
    mma_half(acc, a_thr + 0 * 272, bb0);
    CP_WAIT0(); __syncthreads();
    // iter3: Q0 h1 (b1); prefetch Q1 h0 -> b0
    cpasyncH(smb, 0, g_pack + PQ4 + 8192, tid);
    mma_half(acc, a_thr + 0 * 272 + 128, bb1);
    CP_WAIT0(); __syncthreads();
    // iter4: Q1 h0 (b0); prefetch Q1 h1 -> b1
    cpasyncH(smb, 1, g_pack + PQ4 + 12288, tid);
    mma_half(acc, a_thr + 1 * 272, bb0);
    CP_WAIT0(); __syncthreads();
    // iter5: Q1 h1 (b1); prefetch Q2 h0 -> b0
    cpasyncH(smb, 0, g_pack + PQ4 + 16384, tid);
    mma_half(acc, a_thr + 1 * 272 + 128, bb1);
    CP_WAIT0(); __syncthreads();
    // iter6: Q2 h0 (b0); prefetch Q2 h1 -> b1
    cpasyncH(smb, 1, g_pack + PQ4 + 20480, tid);
    mma_half(acc, a_thr + 2 * 272, bb0);
    CP_WAIT0(); __syncthreads();
    // iter7: Q2 h1 (b1); prefetch K0 h0 -> b0
    cpasyncH(smb, 0, g_pack + PK4, tid);
    mma_half(acc, a_thr + 2 * 272 + 128, bb1);
    epi_s(smc, S_QP_B, bq, 0.25f, acc, lane, mg, ng);
    CP_WAIT0(); __syncthreads();
    // input switch: query -> key
    load_input(smc, key + base, tid);
    __syncthreads();

    zacc(acc);
    // iter8: K0 h0 (b0); prefetch K0 h1 -> b1
    cpasyncH(smb, 1, g_pack + PK4 + 4096, tid);
    mma_half(acc, a_thr + 1 * 272, bb0);
    CP_WAIT0(); __syncthreads();
    // iter9: K0 h1 (b1); prefetch K1 h0 -> b0
    cpasyncH(smb, 0, g_pack + PK4 + 8192, tid);
    mma_half(acc, a_thr + 1 * 272 + 128, bb1);
    CP_WAIT0(); __syncthreads();
    // iter10: K1 h0 (b0); prefetch K1 h1 -> b1
    cpasyncH(smb, 1, g_pack + PK4 + 12288, tid);
    mma_half(acc, a_thr + 2 * 272, bb0);
    CP_WAIT0(); __syncthreads();
    // iter11: K1 h1 (b1); prefetch K2 h0 -> b0
    cpasyncH(smb, 0, g_pack + PK4 + 16384, tid);
    mma_half(acc, a_thr + 2 * 272 + 128, bb1);
    CP_WAIT0(); __syncthreads();
    // iter12: K2 h0 (b0); prefetch K2 h1 -> b1
    cpasyncH(smb, 1, g_pack + PK4 + 20480, tid);
    mma_half(acc, a_thr + 3 * 272, bb0);
    CP_WAIT0(); __syncthreads();
    // iter13: K2 h1 (b1); prefetch O h0 -> b0 (lands under attention)
    cpasyncH(smb, 0, g_pack + PO4, tid);
    mma_half(acc, a_thr + 3 * 272 + 128, bb1);
    epi_s(smc, S_KT_B, bk, 1.0f, acc, lane, mg, ng);
    __syncthreads();                        // KT/QP/VT visible; b1 reads done
    cpasyncH(smb, 1, g_pack + PO4 + 4096, tid);  // O h1 -> b1 (under attention)

    // ---- attention: warp = head wid; two 32-row passes ----
    {
        const int h = wid;
        const int r = lane >> 2, c = lane & 3;
        const uint32_t kt_thr = smb + S_KT_B
            + (uint32_t)((((lane >> 4) << 3) + (lane & 7)) * 272
                         + h * 32 + ((lane >> 3) & 1) * 16);
        const uint32_t vt_thr = smb + S_VT_B
            + (uint32_t)(((((lane >> 3) & 1) << 3) + (lane & 7)) * 272
                         + h * 32 + (lane >> 4) * 16);
#pragma unroll 1
        for (int rh = 0; rh < 2; rh++) {
            const int mh = rh * 32;
            float pa[2][8][4];
#pragma unroll
            for (int mt = 0; mt < 2; mt++)
#pragma unroll
                for (int nt = 0; nt < 8; nt++)
#pragma unroll
                    for (int i = 0; i < 4; i++) pa[mt][nt][i] = 0.f;

            // QK^T: A frags for both mt, K B-frags hoisted over mt
            uint32_t A[2][4];
#pragma unroll
            for (int mt = 0; mt < 2; mt++)
                ldsm4(A[mt], smb + S_QP_B
                         + (uint32_t)((mh + mt * 16 + (lane & 15)) * 272
                                      + h * 32 + (lane >> 4) * 16));
#pragma unroll
            for (int ntp = 0; ntp < 4; ntp++) {
                uint32_t Bf[4];
                ldsm4(Bf, kt_thr + (uint32_t)(ntp * 16 * 272));
#pragma unroll
                for (int mt = 0; mt < 2; mt++) {
                    mma16(pa[mt][2 * ntp], A[mt], Bf[0], Bf[1]);
                    mma16(pa[mt][2 * ntp + 1], A[mt], Bf[2], Bf[3]);
                }
            }

            // masked softmax
            float inv[2][2];
#pragma unroll
            for (int mt = 0; mt < 2; mt++) {
                ull mA = *(const ull*)(smc + S_MSK_B + (mh + mt * 16 + r) * 8);
                ull mB = *(const ull*)(smc + S_MSK_B + (mh + mt * 16 + r + 8) * 8);
                float mxA = -3.0e38f, mxB = -3.0e38f;
#pragma unroll
                for (int nt = 0; nt < 8; nt++) {
                    int c0 = nt * 8 + 2 * c, c1 = c0 + 1;
                    float v;
                    v = ((mA >> c0) & 1) ? pa[mt][nt][0] : -1.0e9f; pa[mt][nt][0] = v; mxA = fmaxf(mxA, v);
                    v = ((mA >> c1) & 1) ? pa[mt][nt][1] : -1.0e9f; pa[mt][nt][1] = v; mxA = fmaxf(mxA, v);
                    v = ((mB >> c0) & 1) ? pa[mt][nt][2] : -1.0e9f; pa[mt][nt][2] = v; mxB = fmaxf(mxB, v);
                    v = ((mB >> c1) & 1) ? pa[mt][nt][3] : -1.0e9f; pa[mt][nt][3] = v; mxB = fmaxf(mxB, v);
                }
                mxA = fmaxf(mxA, __shfl_xor_sync(0xffffffffu, mxA, 1));
                mxA = fmaxf(mxA, __shfl_xor_sync(0xffffffffu, mxA, 2));
                mxB = fmaxf(mxB, __shfl_xor_sync(0xffffffffu, mxB, 1));
                mxB = fmaxf(mxB, __shfl_xor_sync(0xffffffffu, mxB, 2));
                float sA = 0.f, sB = 0.f;
#pragma unroll
                for (int nt = 0; nt < 8; nt++) {
                    float e;
                    e = __expf(pa[mt][nt][0] - mxA); pa[mt][nt][0] = e; sA += e;
                    e = __expf(pa[mt][nt][1] - mxA); pa[mt][nt][1] = e; sA += e;
                    e = __expf(pa[mt][nt][2] - mxB); pa[mt][nt][2] = e; sB += e;
                    e = __expf(pa[mt][nt][3] - mxB); pa[mt][nt][3] = e; sB += e;
                }
                sA += __shfl_xor_sync(0xffffffffu, sA, 1);
                sA += __shfl_xor_sync(0xffffffffu, sA, 2);
                sB += __shfl_xor_sync(0xffffffffu, sB, 1);
                sB += __shfl_xor_sync(0xffffffffu, sB, 2);
                inv[mt][0] = 1.0f / sA;
                inv[mt][1] = 1.0f / sB;
            }

            // P @ V: V B-frags hoisted over mt
            float xacc[2][2][4];
#pragma unroll
            for (int mt = 0; mt < 2; mt++)
#pragma unroll
                for (int n2 = 0; n2 < 2; n2++)
#pragma unroll
                    for (int i = 0; i < 4; i++) xacc[mt][n2][i] = 0.f;
#pragma unroll
            for (int kp = 0; kp < 4; kp++) {
                uint32_t Vf[4];
                ldsm4t(Vf, vt_thr + (uint32_t)(kp * 16 * 272));
#pragma unroll
                for (int mt = 0; mt < 2; mt++) {
                    uint32_t Ax[4];
                    Ax[0] = h2(pa[mt][2 * kp][0], pa[mt][2 * kp][1]);
                    Ax[1] = h2(pa[mt][2 * kp][2], pa[mt][2 * kp][3]);
                    Ax[2] = h2(pa[mt][2 * kp + 1][0], pa[mt][2 * kp + 1][1]);
                    Ax[3] = h2(pa[mt][2 * kp + 1][2], pa[mt][2 * kp + 1][3]);
                    mma16(xacc[mt][0], Ax, Vf[0], Vf[1]);
                    mma16(xacc[mt][1], Ax, Vf[2], Vf[3]);
                }
            }

            // x (normalized, fp16) -> S_IN rows t+2
#pragma unroll
            for (int mt = 0; mt < 2; mt++) {
                int rA = mh + mt * 16 + r, rB = rA + 8;
                float iA = inv[mt][0], iB = inv[mt][1];
#pragma unroll
                for (int n2 = 0; n2 < 2; n2++) {
                    int col = h * 16 + n2 * 8 + 2 * c;
                    *(uint32_t*)(smc + S_IN_B + (2 + rA) * 272 + col * 2) =
                        h2(xacc[mt][n2][0] * iA, xacc[mt][n2][1] * iA);
                    *(uint32_t*)(smc + S_IN_B + (2 + rB) * 272 + col * 2) =
                        h2(xacc[mt][n2][2] * iB, xacc[mt][n2][3] * iB);
                }
            }
        }
    }
    CP_WAIT0();
    __syncthreads();                        // x rows + both O halves visible

    // ---- O-projection: both halves back-to-back ----
    zacc(acc);
    mma_half(acc, a_thr + 2 * 272, bb0);
    mma_half(acc, a_thr + 2 * 272 + 128, bb1);
    epi_g(out + base, bo, acc, lane, mg, ng);
}

extern "C" void kernel_launch(void* const* d_in, const int* in_sizes, int n_in,
                              void* d_out, int out_size) {
    (void)in_sizes; (void)n_in; (void)out_size;
    const float* query = (const float*)d_in[0];
    const float* key   = (const float*)d_in[1];
    const float* value = (const float*)d_in[2];
    const int*   mask  = (const int*)d_in[3];
    const float* Wq = (const float*)d_in[4];
    const float* bq = (const float*)d_in[5];
    const float* Wk = (const float*)d_in[6];
    const float* bk = (const float*)d_in[7];
    const float* Wv = (const float*)d_in[8];
    const float* bv = (const float*)d_in[9];
    const float* Wo = (const float*)d_in[10];
    const float* bo = (const float*)d_in[11];
    float* out = (float*)d_out;

    cudaFuncSetAttribute(attn_kernel, cudaFuncAttributeMaxDynamicSharedMemorySize, SMEM_BYTES);
    prep_kernel<<<64, 256>>>(Wq, Wk, Wv, Wo);
    attn_kernel<<<4096, 256, SMEM_BYTES>>>(query, key, value, mask, bq, bk, bv, bo, out);
}